// round 12
// baseline (speedup 1.0000x reference)
#include <cuda_runtime.h>
#include <cuda_bf16.h>
#include <math.h>
#include <stdint.h>

// ---------------------------------------------------------------------------
// Problem constants
// ---------------------------------------------------------------------------
constexpr int cV  = 32000;
constexpr int cD  = 768;
constexpr int cH  = 12;
constexpr int cL  = 8;
constexpr int cT  = 1024;
constexpr int cB  = 4;
constexpr int cHD = cD / cH;          // 64
constexpr int cM  = cB * cT;          // 4096
constexpr int cD3 = 3 * cD;           // 2304
constexpr int cDF = 4 * cD;           // 3072
constexpr int cZ  = cB * cH;          // 48 heads
constexpr int cVT = cV / 128;         // 250 head n-tiles
constexpr size_t cQH = (size_t)cT * cHD;       // 65536 per head

// ---------------------------------------------------------------------------
// Scratch (device globals — no allocation allowed)
// ---------------------------------------------------------------------------
__device__ float g_x  [cM * cD];
__device__ float g_nll[cM];
__device__ float2 g_part[(size_t)cVT * cM];    // head loss partials (max,sumexp)

__device__ __nv_bfloat16 g_ln_h[cM * cD],  g_ln_l[cM * cD];
__device__ __nv_bfloat16 g_y_h [cM * cD],  g_y_l [cM * cD];
__device__ __nv_bfloat16 g_fc_h[cM * cDF], g_fc_l[cM * cDF];
__device__ __nv_bfloat16 g_q_h [cZ * cT * cHD], g_q_l [cZ * cT * cHD];
__device__ __nv_bfloat16 g_k_h [cZ * cT * cHD], g_k_l [cZ * cT * cHD];
__device__ __nv_bfloat16 g_v_h [cZ * cT * cHD], g_v_l [cZ * cT * cHD];
__device__ __nv_bfloat16 g_wa_h[cL * cD * cD3], g_wa_l[cL * cD * cD3];
__device__ __nv_bfloat16 g_wp_h[cL * cD * cD],  g_wp_l[cL * cD * cD];
__device__ __nv_bfloat16 g_wf_h[cL * cD * cDF], g_wf_l[cL * cD * cDF];
__device__ __nv_bfloat16 g_wo_h[cL * cDF * cD], g_wo_l[cL * cDF * cD];
__device__ __nv_bfloat16 g_wh_h[cD * cV],       g_wh_l[cD * cV];

// ---------------------------------------------------------------------------
// PTX helpers
// ---------------------------------------------------------------------------
__device__ __forceinline__ void cp_async16(uint32_t saddr, const void* gptr) {
    asm volatile("cp.async.cg.shared.global [%0], [%1], 16;"
                 :: "r"(saddr), "l"(gptr));
}
#define CP_COMMIT() asm volatile("cp.async.commit_group;" ::: "memory")
#define CP_WAIT0()  asm volatile("cp.async.wait_group 0;" ::: "memory")
#define CP_WAIT1()  asm volatile("cp.async.wait_group 1;" ::: "memory")

__device__ __forceinline__ void ldsm_x4(uint32_t* r, uint32_t addr) {
    asm volatile("ldmatrix.sync.aligned.m8n8.x4.shared.b16 {%0,%1,%2,%3}, [%4];"
        : "=r"(r[0]), "=r"(r[1]), "=r"(r[2]), "=r"(r[3]) : "r"(addr));
}
__device__ __forceinline__ void ldsm_x4_t(uint32_t* r, uint32_t addr) {
    asm volatile("ldmatrix.sync.aligned.m8n8.x4.trans.shared.b16 {%0,%1,%2,%3}, [%4];"
        : "=r"(r[0]), "=r"(r[1]), "=r"(r[2]), "=r"(r[3]) : "r"(addr));
}
__device__ __forceinline__ void mma_bf16(float* d, const uint32_t* a,
                                         uint32_t b0, uint32_t b1) {
    asm volatile(
        "mma.sync.aligned.m16n8k16.row.col.f32.bf16.bf16.f32 "
        "{%0,%1,%2,%3},{%4,%5,%6,%7},{%8,%9},{%0,%1,%2,%3};"
        : "+f"(d[0]), "+f"(d[1]), "+f"(d[2]), "+f"(d[3])
        : "r"(a[0]), "r"(a[1]), "r"(a[2]), "r"(a[3]), "r"(b0), "r"(b1));
}

__device__ __forceinline__ uint32_t pack_bf16x2(float lo, float hi) {
    uint32_t d;
    asm("cvt.rn.bf16x2.f32 %0, %1, %2;" : "=r"(d) : "f"(hi), "f"(lo));
    return d;
}
__device__ __forceinline__ void split2(float v0, float v1,
                                       uint32_t& hp, uint32_t& lp) {
    hp = pack_bf16x2(v0, v1);
    float h0 = __uint_as_float(hp << 16);
    float h1 = __uint_as_float(hp & 0xffff0000u);
    lp = pack_bf16x2(v0 - h0, v1 - h1);
}

__device__ __forceinline__ float gelu_exact(float x) {
    return 0.5f * x * (1.0f + erff(x * 0.70710678118654752f));
}

// ---------------------------------------------------------------------------
// Generalized split-bf16 GEMM (3-mma Markidis): C = A @ W(op)
// 3-stage cp.async pipeline; staging issued at TOP of iteration so the DMA
// window spans ~2 compute iterations instead of 1.
// LOSSP: fuse per-tile (max, sum-exp) partials into the epilogue (head GEMM).
// ---------------------------------------------------------------------------
template<int NT, bool BTRANS>
struct Geom {
    static constexpr int SBb = BTRANS ? (2 * NT + 16) : 80;
    static constexpr int BSZ = BTRANS ? 32 * SBb : NT * 80;
    static constexpr int AL  = 10240;
    static constexpr int BH  = 20480;
    static constexpr int BL  = BH + BSZ;
    static constexpr int BUF = BH + 2 * BSZ;
    static constexpr int SMEM = 3 * BUF;          // 3 stages
};

template<int NT, bool BTRANS, bool BIAS, bool RES, bool GELU,
         bool WC, bool WPL, int ZMODE, bool SWAPXY, bool LOSSP>
__global__ void __launch_bounds__(256, 2) gemm_u(
    const __nv_bfloat16* __restrict__ Ah, const __nv_bfloat16* __restrict__ Al,
    const __nv_bfloat16* __restrict__ Wh, const __nv_bfloat16* __restrict__ Wl,
    const float* __restrict__ bias, const float* __restrict__ Rres,
    float* __restrict__ C,
    __nv_bfloat16* __restrict__ Ch, __nv_bfloat16* __restrict__ Cl,
    __nv_bfloat16* __restrict__ Dh, __nv_bfloat16* __restrict__ Dl,
    __nv_bfloat16* __restrict__ Eh, __nv_bfloat16* __restrict__ El,
    int N, int K, int ldc, size_t sA, size_t sW, size_t sC) {

    using G = Geom<NT, BTRANS>;
    extern __shared__ char smem[];
    const uint32_t sb = (uint32_t)__cvta_generic_to_shared(smem);

    const int m0 = (SWAPXY ? blockIdx.x : blockIdx.y) * 128;
    const int n0 = (SWAPXY ? blockIdx.y : blockIdx.x) * NT;

    const int z = blockIdx.z;
    Ah += z * sA; Al += z * sA;
    Wh += z * sW; Wl += z * sW;
    const size_t cofs = z * sC;

    const int tid  = threadIdx.x;
    const int lane = tid & 31;
    const int wid  = tid >> 5;
    const int gr   = lane >> 2;
    const int tg   = lane & 3;
    const int mw   = (wid & 3) * 32;
    const int nw   = (wid >> 2) * (NT / 2);
    const int lr   = lane & 7, lt = lane >> 3;

    const uint32_t aoff = (uint32_t)((mw + (lt & 1) * 8 + lr) * 80 + (lt >> 1) * 16);
    uint32_t boff;
    if (BTRANS) boff = (uint32_t)(((lt & 1) * 8 + lr) * G::SBb + (nw + (lt >> 1) * 8) * 2);
    else        boff = (uint32_t)((nw + (lt >> 1) * 8 + lr) * 80 + (lt & 1) * 16);

    constexpr int NTW = NT / 16;
    float acc[2][NTW][4];
    #pragma unroll
    for (int mi = 0; mi < 2; mi++)
        #pragma unroll
        for (int nt = 0; nt < NTW; nt++)
            #pragma unroll
            for (int q = 0; q < 4; q++) acc[mi][nt][q] = 0.0f;

    const int NK = K >> 5;

    auto stage = [&](int ib, int buf) {
        const int k0 = ib << 5;
        const uint32_t bb = sb + buf * G::BUF;
        #pragma unroll
        for (int j = 0; j < 2; j++) {
            int c = tid + 256 * j;
            int row = c >> 2, seg = c & 3;
            uint32_t d = bb + (uint32_t)(row * 80 + seg * 16);
            size_t s = (size_t)(m0 + row) * K + k0 + seg * 8;
            cp_async16(d, Ah + s);
            cp_async16(d + G::AL, Al + s);
        }
        if (BTRANS) {
            constexpr int SEGS = NT / 8;
            constexpr int BCH = 32 * SEGS;
            #pragma unroll
            for (int j = 0; j < (BCH + 255) / 256; j++) {
                int c = tid + 256 * j;
                if ((BCH % 256 == 0) || c < BCH) {
                    int kr = c / SEGS, seg = c - kr * SEGS;
                    uint32_t d = bb + G::BH + (uint32_t)(kr * G::SBb + seg * 16);
                    size_t s = (size_t)(k0 + kr) * N + n0 + seg * 8;
                    cp_async16(d, Wh + s);
                    cp_async16(d + G::BSZ, Wl + s);
                }
            }
        } else {
            constexpr int BCH = NT * 4;
            #pragma unroll
            for (int j = 0; j < (BCH + 255) / 256; j++) {
                int c = tid + 256 * j;
                if ((BCH % 256 == 0) || c < BCH) {
                    int row = c >> 2, seg = c & 3;
                    uint32_t d = bb + G::BH + (uint32_t)(row * 80 + seg * 16);
                    size_t s = (size_t)(n0 + row) * K + k0 + seg * 8;
                    cp_async16(d, Wh + s);
                    cp_async16(d + G::BSZ, Wl + s);
                }
            }
        }
    };

    stage(0, 0); CP_COMMIT();
    stage(1, 1); CP_COMMIT();

    for (int ib = 0; ib < NK; ib++) {
        const int buf = ib % 3;
        CP_WAIT1();
        __syncthreads();

        // Stage EARLY (top of iteration): the DMA for buffer ib+2 overlaps
        // this iteration's compute AND the next one's. Hazard-free: buffer
        // (ib+2)%3 was consumed in iteration ib-1, and every warp passed this
        // iteration's __syncthreads after finishing that compute.
        // Unconditional commit keeps wait_group 1 tail bookkeeping sound.
        if (ib + 2 < NK) stage(ib + 2, (ib + 2) % 3);
        CP_COMMIT();

        const uint32_t base = sb + buf * G::BUF;
        const uint32_t aHb = base + aoff;
        const uint32_t aLb = base + G::AL + aoff;
        const uint32_t bHb = base + G::BH + boff;
        const uint32_t bLb = base + G::BL + boff;

        #pragma unroll
        for (int ks = 0; ks < 2; ks++) {
            uint32_t ahi[2][4], alo[2][4];
            ldsm_x4(ahi[0], aHb + ks * 32);
            ldsm_x4(ahi[1], aHb + 1280 + ks * 32);
            ldsm_x4(alo[0], aLb + ks * 32);
            ldsm_x4(alo[1], aLb + 1280 + ks * 32);
            #pragma unroll
            for (int g = 0; g < NT / 32; g++) {
                uint32_t bh[4], bl[4];
                if (BTRANS) {
                    ldsm_x4_t(bh, bHb + ks * (16 * G::SBb) + g * 32);
                    ldsm_x4_t(bl, bLb + ks * (16 * G::SBb) + g * 32);
                } else {
                    ldsm_x4(bh, bHb + ks * 32 + g * 1280);
                    ldsm_x4(bl, bLb + ks * 32 + g * 1280);
                }
                const int nt = g * 2;
                mma_bf16(acc[0][nt],     ahi[0], bh[0], bh[1]);
                mma_bf16(acc[1][nt],     ahi[1], bh[0], bh[1]);
                mma_bf16(acc[0][nt + 1], ahi[0], bh[2], bh[3]);
                mma_bf16(acc[1][nt + 1], ahi[1], bh[2], bh[3]);
                mma_bf16(acc[0][nt],     ahi[0], bl[0], bl[1]);
                mma_bf16(acc[1][nt],     ahi[1], bl[0], bl[1]);
                mma_bf16(acc[0][nt + 1], ahi[0], bl[2], bl[3]);
                mma_bf16(acc[1][nt + 1], ahi[1], bl[2], bl[3]);
                mma_bf16(acc[0][nt],     alo[0], bh[0], bh[1]);
                mma_bf16(acc[1][nt],     alo[1], bh[0], bh[1]);
                mma_bf16(acc[0][nt + 1], alo[0], bh[2], bh[3]);
                mma_bf16(acc[1][nt + 1], alo[1], bh[2], bh[3]);
            }
        }
    }

    #pragma unroll
    for (int mi = 0; mi < 2; mi++) {
        const int r0 = m0 + mw + mi * 16 + gr;
        #pragma unroll
        for (int nt = 0; nt < NTW; nt++) {
            const int c0 = n0 + nw + nt * 8 + tg * 2;
            float2 v0 = make_float2(acc[mi][nt][0], acc[mi][nt][1]);
            float2 v1 = make_float2(acc[mi][nt][2], acc[mi][nt][3]);
            if (BIAS) {
                float2 bv = *(const float2*)(bias + c0);
                v0.x += bv.x; v0.y += bv.y;
                v1.x += bv.x; v1.y += bv.y;
            }
            if (GELU) {
                v0.x = gelu_exact(v0.x); v0.y = gelu_exact(v0.y);
                v1.x = gelu_exact(v1.x); v1.y = gelu_exact(v1.y);
            }
            if (ZMODE == 2) {
                const int sec = n0 / cD;
                const int cc  = c0 - sec * cD;
                const int h   = cc >> 6, d = cc & 63;
                const float scale = (sec == 0) ? 0.125f : 1.0f;
                uint32_t* ph = (uint32_t*)(sec == 0 ? Ch : sec == 1 ? Dh : Eh);
                uint32_t* pl = (uint32_t*)(sec == 0 ? Cl : sec == 1 ? Dl : El);
                const int b = r0 >> 10, t0 = r0 & 1023;
                size_t zb = (size_t)(b * cH + h) * 1024;
                size_t oA = (zb + t0)     * 32 + (d >> 1);
                size_t oB = (zb + t0 + 8) * 32 + (d >> 1);
                uint32_t hp, lp;
                split2(v0.x * scale, v0.y * scale, hp, lp);
                ph[oA] = hp; pl[oA] = lp;
                split2(v1.x * scale, v1.y * scale, hp, lp);
                ph[oB] = hp; pl[oB] = lp;
            } else {
                size_t o0 = cofs + (size_t)r0 * ldc + c0;
                size_t o1 = cofs + (size_t)(r0 + 8) * ldc + c0;
                if (RES) {
                    float2 a0 = *(const float2*)(Rres + o0);
                    float2 a1 = *(const float2*)(Rres + o1);
                    v0.x += a0.x; v0.y += a0.y;
                    v1.x += a1.x; v1.y += a1.y;
                }
                if (WC) {
                    *(float2*)(C + o0) = v0;
                    *(float2*)(C + o1) = v1;
                }
                if (WPL) {
                    uint32_t hp, lp;
                    split2(v0.x, v0.y, hp, lp);
                    ((uint32_t*)Ch)[o0 >> 1] = hp;
                    ((uint32_t*)Cl)[o0 >> 1] = lp;
                    split2(v1.x, v1.y, hp, lp);
                    ((uint32_t*)Ch)[o1 >> 1] = hp;
                    ((uint32_t*)Cl)[o1 >> 1] = lp;
                }
            }
        }
    }

    if (LOSSP) {
        // per-tile (max, sum-exp) partials over this CTA's NT columns,
        // computed from acc (values still live), written to g_part.
        float pm[2][2], ps[2][2];
        #pragma unroll
        for (int mi = 0; mi < 2; mi++) {
            #pragma unroll
            for (int rh = 0; rh < 2; rh++) {
                float m = -INFINITY;
                #pragma unroll
                for (int nt = 0; nt < NTW; nt++)
                    m = fmaxf(m, fmaxf(acc[mi][nt][rh * 2], acc[mi][nt][rh * 2 + 1]));
                float s = 0.0f;
                #pragma unroll
                for (int nt = 0; nt < NTW; nt++)
                    s += __expf(acc[mi][nt][rh * 2] - m)
                       + __expf(acc[mi][nt][rh * 2 + 1] - m);
                #pragma unroll
                for (int o = 1; o <= 2; o <<= 1) {
                    float mo = __shfl_xor_sync(0xffffffffu, m, o);
                    float so = __shfl_xor_sync(0xffffffffu, s, o);
                    float nm = fmaxf(m, mo);
                    s = s * __expf(m - nm) + so * __expf(mo - nm);
                    m = nm;
                }
                pm[mi][rh] = m; ps[mi][rh] = s;
            }
        }
        __syncthreads();
        float* sp = (float*)smem;                // [2 halves][128 rows][2]
        if (tg == 0) {
            int half = wid >> 2;
            #pragma unroll
            for (int mi = 0; mi < 2; mi++)
                #pragma unroll
                for (int rh = 0; rh < 2; rh++) {
                    int row = mw + mi * 16 + gr + rh * 8;
                    sp[(half * 128 + row) * 2 + 0] = pm[mi][rh];
                    sp[(half * 128 + row) * 2 + 1] = ps[mi][rh];
                }
        }
        __syncthreads();
        if (tid < 128) {
            float m0v = sp[tid * 2],           s0v = sp[tid * 2 + 1];
            float m1v = sp[(128 + tid) * 2],   s1v = sp[(128 + tid) * 2 + 1];
            float nm = fmaxf(m0v, m1v);
            float sc = s0v * __expf(m0v - nm) + s1v * __expf(m1v - nm);
            g_part[(size_t)(n0 >> 7) * cM + (m0 + tid)] = make_float2(nm, sc);
        }
    }
}

// ---------------------------------------------------------------------------
// Fused flash attention (split-bf16 mma, online softmax)
// ---------------------------------------------------------------------------
constexpr int F_SQ   = 144;
constexpr int F_PL   = 128 * F_SQ;
constexpr int F_KV0  = 2 * F_PL;
constexpr int F_KVSZ = 4 * F_PL;
constexpr int FLASH_SMEM = 2 * F_PL + 2 * F_KVSZ;  // 184320

__global__ void __launch_bounds__(256, 1) flash_kernel(
    const __nv_bfloat16* __restrict__ qh, const __nv_bfloat16* __restrict__ ql,
    const __nv_bfloat16* __restrict__ kh, const __nv_bfloat16* __restrict__ kl,
    const __nv_bfloat16* __restrict__ vh, const __nv_bfloat16* __restrict__ vl,
    __nv_bfloat16* __restrict__ yh, __nv_bfloat16* __restrict__ yl) {

    extern __shared__ char smem[];
    const uint32_t sb = (uint32_t)__cvta_generic_to_shared(smem);
    const int qb = blockIdx.x;
    const int z  = blockIdx.y;
    const int q0 = qb * 128;
    const int tid  = threadIdx.x;
    const int lane = tid & 31;
    const int wid  = tid >> 5;
    const int gr   = lane >> 2;
    const int tg   = lane & 3;
    const int wq   = wid * 16;
    const int lr   = lane & 7, lt = lane >> 3;

    const __nv_bfloat16* qhz = qh + (size_t)z * cQH;
    const __nv_bfloat16* qlz = ql + (size_t)z * cQH;
    const __nv_bfloat16* khz = kh + (size_t)z * cQH;
    const __nv_bfloat16* klz = kl + (size_t)z * cQH;
    const __nv_bfloat16* vhz = vh + (size_t)z * cQH;
    const __nv_bfloat16* vlz = vl + (size_t)z * cQH;

    #pragma unroll
    for (int j = 0; j < 4; j++) {
        int c = tid + 256 * j;
        int row = c >> 3, seg = c & 7;
        uint32_t d = sb + (uint32_t)(row * F_SQ + seg * 16);
        size_t s = (size_t)(q0 + row) * cHD + seg * 8;
        cp_async16(d, qhz + s);
        cp_async16(d + F_PL, qlz + s);
    }
    auto stageKV = [&](int kb, int buf) {
        const uint32_t bb = sb + F_KV0 + buf * F_KVSZ;
        #pragma unroll
        for (int j = 0; j < 4; j++) {
            int c = tid + 256 * j;
            int row = c >> 3, seg = c & 7;
            uint32_t d = bb + (uint32_t)(row * F_SQ + seg * 16);
            size_t s = (size_t)(kb * 128 + row) * cHD + seg * 8;
            cp_async16(d, khz + s);
            cp_async16(d + F_PL, klz + s);
            cp_async16(d + 2 * F_PL, vhz + s);
            cp_async16(d + 3 * F_PL, vlz + s);
        }
    };

    stageKV(0, 0);
    CP_COMMIT();
    if (qb >= 1) { stageKV(1, 1); CP_COMMIT(); }

    float mrow[2] = { -INFINITY, -INFINITY };
    float lrow[2] = { 0.0f, 0.0f };
    float oacc[8][4];
    #pragma unroll
    for (int nt = 0; nt < 8; nt++)
        #pragma unroll
        for (int q = 0; q < 4; q++) oacc[nt][q] = 0.0f;

    uint32_t qfh[4][4], qfl[4][4];
    bool qloaded = false;

    const uint32_t q_aoff = (uint32_t)((wq + (lt & 1) * 8 + lr) * F_SQ + (lt >> 1) * 16);
    const uint32_t k_boff = (uint32_t)(((lt >> 1) * 8 + lr) * F_SQ + (lt & 1) * 16);
    const uint32_t v_boff = (uint32_t)(((lt & 1) * 8 + lr) * F_SQ + (lt >> 1) * 16);

    for (int kb = 0; kb <= qb; kb++) {
        if (kb < qb) { CP_WAIT1(); } else { CP_WAIT0(); }
        __syncthreads();

        if (!qloaded) {
            #pragma unroll
            for (int ks = 0; ks < 4; ks++) {
                ldsm_x4(qfh[ks], sb + q_aoff + ks * 32);
                ldsm_x4(qfl[ks], sb + F_PL + q_aoff + ks * 32);
            }
            qloaded = true;
        }

        const uint32_t kvb = sb + F_KV0 + (kb & 1) * F_KVSZ;

        float s[16][4];
        #pragma unroll
        for (int nt = 0; nt < 16; nt++)
            #pragma unroll
            for (int q = 0; q < 4; q++) s[nt][q] = 0.0f;

        #pragma unroll
        for (int ks = 0; ks < 4; ks++) {
            #pragma unroll
            for (int g = 0; g < 8; g++) {
                uint32_t bh[4], bl[4];
                uint32_t addr = kvb + k_boff + (uint32_t)(g * 16 * F_SQ) + ks * 32;
                ldsm_x4(bh, addr);
                ldsm_x4(bl, addr + F_PL);
                const int nt = g * 2;
                mma_bf16(s[nt],     qfh[ks], bh[0], bh[1]);
                mma_bf16(s[nt + 1], qfh[ks], bh[2], bh[3]);
                mma_bf16(s[nt],     qfh[ks], bl[0], bl[1]);
                mma_bf16(s[nt + 1], qfh[ks], bl[2], bl[3]);
                mma_bf16(s[nt],     qfl[ks], bh[0], bh[1]);
                mma_bf16(s[nt + 1], qfl[ks], bh[2], bh[3]);
            }
        }

        if (kb == qb) {
            const int r0 = wq + gr, r1 = wq + gr + 8;
            #pragma unroll
            for (int nt = 0; nt < 16; nt++) {
                const int c0 = nt * 8 + tg * 2;
                if (c0     > r0) s[nt][0] = -1e30f;
                if (c0 + 1 > r0) s[nt][1] = -1e30f;
                if (c0     > r1) s[nt][2] = -1e30f;
                if (c0 + 1 > r1) s[nt][3] = -1e30f;
            }
        }

        float mn0 = -INFINITY, mn1 = -INFINITY;
        #pragma unroll
        for (int nt = 0; nt < 16; nt++) {
            mn0 = fmaxf(mn0, fmaxf(s[nt][0], s[nt][1]));
            mn1 = fmaxf(mn1, fmaxf(s[nt][2], s[nt][3]));
        }
        mn0 = fmaxf(mn0, __shfl_xor_sync(0xffffffffu, mn0, 1));
        mn0 = fmaxf(mn0, __shfl_xor_sync(0xffffffffu, mn0, 2));
        mn1 = fmaxf(mn1, __shfl_xor_sync(0xffffffffu, mn1, 1));
        mn1 = fmaxf(mn1, __shfl_xor_sync(0xffffffffu, mn1, 2));
        float mnew0 = fmaxf(mrow[0], mn0);
        float mnew1 = fmaxf(mrow[1], mn1);
        float al0 = __expf(mrow[0] - mnew0);
        float al1 = __expf(mrow[1] - mnew1);
        mrow[0] = mnew0; mrow[1] = mnew1;

        float rs0 = 0.0f, rs1 = 0.0f;
        #pragma unroll
        for (int nt = 0; nt < 16; nt++) {
            s[nt][0] = __expf(s[nt][0] - mnew0);
            s[nt][1] = __expf(s[nt][1] - mnew0);
            s[nt][2] = __expf(s[nt][2] - mnew1);
            s[nt][3] = __expf(s[nt][3] - mnew1);
            rs0 += s[nt][0] + s[nt][1];
            rs1 += s[nt][2] + s[nt][3];
        }
        rs0 += __shfl_xor_sync(0xffffffffu, rs0, 1);
        rs0 += __shfl_xor_sync(0xffffffffu, rs0, 2);
        rs1 += __shfl_xor_sync(0xffffffffu, rs1, 1);
        rs1 += __shfl_xor_sync(0xffffffffu, rs1, 2);
        lrow[0] = lrow[0] * al0 + rs0;
        lrow[1] = lrow[1] * al1 + rs1;

        #pragma unroll
        for (int nt = 0; nt < 8; nt++) {
            oacc[nt][0] *= al0; oacc[nt][1] *= al0;
            oacc[nt][2] *= al1; oacc[nt][3] *= al1;
        }

        #pragma unroll
        for (int ks = 0; ks < 8; ks++) {
            uint32_t pah[4], pal[4];
            uint32_t h0, l0;
            split2(s[2*ks][0],   s[2*ks][1],   h0, l0); pah[0] = h0; pal[0] = l0;
            split2(s[2*ks][2],   s[2*ks][3],   h0, l0); pah[1] = h0; pal[1] = l0;
            split2(s[2*ks+1][0], s[2*ks+1][1], h0, l0); pah[2] = h0; pal[2] = l0;
            split2(s[2*ks+1][2], s[2*ks+1][3], h0, l0); pah[3] = h0; pal[3] = l0;
            #pragma unroll
            for (int g = 0; g < 4; g++) {
                uint32_t bvh[4], bvl[4];
                uint32_t addr = kvb + 2 * F_PL + v_boff
                              + (uint32_t)(ks * 16 * F_SQ) + g * 32;
                ldsm_x4_t(bvh, addr);
                ldsm_x4_t(bvl, addr + F_PL);
                const int nt = g * 2;
                mma_bf16(oacc[nt],     pah, bvh[0], bvh[1]);
                mma_bf16(oacc[nt + 1], pah, bvh[2], bvh[3]);
                mma_bf16(oacc[nt],     pah, bvl[0], bvl[1]);
                mma_bf16(oacc[nt + 1], pah, bvl[2], bvl[3]);
                mma_bf16(oacc[nt],     pal, bvh[0], bvh[1]);
                mma_bf16(oacc[nt + 1], pal, bvh[2], bvh[3]);
            }
        }

        __syncthreads();
        if (kb + 2 <= qb) { stageKV(kb + 2, kb & 1); CP_COMMIT(); }
    }

    const float inv0 = 1.0f / lrow[0];
    const float inv1 = 1.0f / lrow[1];
    const int b = z / cH, h = z % cH;
    const int r0 = b * cT + q0 + wq + gr;
    #pragma unroll
    for (int nt = 0; nt < 8; nt++) {
        const int c0 = h * cHD + nt * 8 + tg * 2;
        uint32_t hp, lp;
        split2(oacc[nt][0] * inv0, oacc[nt][1] * inv0, hp, lp);
        size_t o0 = ((size_t)r0 * cD + c0) >> 1;
        ((uint32_t*)yh)[o0] = hp; ((uint32_t*)yl)[o0] = lp;
        split2(oacc[nt][2] * inv1, oacc[nt][3] * inv1, hp, lp);
        size_t o1 = ((size_t)(r0 + 8) * cD + c0) >> 1;
        ((uint32_t*)yh)[o1] = hp; ((uint32_t*)yl)[o1] = lp;
    }
}

// ---------------------------------------------------------------------------
// Block reductions (blockDim.x == 256)
// ---------------------------------------------------------------------------
__device__ __forceinline__ float blockReduceSum(float v) {
    __shared__ float sh[8];
    #pragma unroll
    for (int o = 16; o; o >>= 1) v += __shfl_xor_sync(0xffffffffu, v, o);
    int w = threadIdx.x >> 5, l = threadIdx.x & 31;
    __syncthreads();
    if (l == 0) sh[w] = v;
    __syncthreads();
    if (w == 0) {
        v = (l < 8) ? sh[l] : 0.0f;
        #pragma unroll
        for (int o = 16; o; o >>= 1) v += __shfl_xor_sync(0xffffffffu, v, o);
        if (l == 0) sh[0] = v;
    }
    __syncthreads();
    return sh[0];
}

// ---------------------------------------------------------------------------
// Small kernels
// ---------------------------------------------------------------------------
__global__ void __launch_bounds__(256) split_kernel(const float* __restrict__ src,
                                                    __nv_bfloat16* __restrict__ hi,
                                                    __nv_bfloat16* __restrict__ lo,
                                                    int nquads) {
    int i = blockIdx.x * blockDim.x + threadIdx.x;
    if (i >= nquads) return;
    float4 v = *(const float4*)(src + (size_t)i * 4);
    uint32_t h0, l0, h1, l1;
    split2(v.x, v.y, h0, l0);
    split2(v.z, v.w, h1, l1);
    ((uint2*)hi)[i] = make_uint2(h0, h1);
    ((uint2*)lo)[i] = make_uint2(l0, l1);
}

__global__ void embed_kernel(const int* __restrict__ idx,
                             const float* __restrict__ wte,
                             const float* __restrict__ wpe,
                             float* __restrict__ x) {
    int i = blockIdx.x * blockDim.x + threadIdx.x;
    int row = i / cD;
    int d   = i - row * cD;
    int t   = row & (cT - 1);
    int tok = idx[row];
    x[i] = wte[(size_t)tok * cD + d] + wpe[(size_t)t * cD + d];
}

__global__ void __launch_bounds__(256) ln_kernel(const float* __restrict__ x,
                                                 const float* __restrict__ g,
                                                 const float* __restrict__ b,
                                                 __nv_bfloat16* __restrict__ oh,
                                                 __nv_bfloat16* __restrict__ ol) {
    const int row = blockIdx.x;
    const float* xr = x + (size_t)row * cD;
    const int t = threadIdx.x;
    float v0 = xr[t], v1 = xr[t + 256], v2 = xr[t + 512];
    float s  = blockReduceSum(v0 + v1 + v2);
    float s2 = blockReduceSum(v0 * v0 + v1 * v1 + v2 * v2);
    const float inv = 1.0f / cD;
    float mu  = s * inv;
    float var = s2 * inv - mu * mu;
    float rs  = rsqrtf(var + 1e-5f);
    #pragma unroll
    for (int j = 0; j < 3; j++) {
        int d = t + j * 256;
        float val = (((j == 0) ? v0 : (j == 1) ? v1 : v2) - mu) * rs * g[d] + b[d];
        __nv_bfloat16 h = __float2bfloat16_rn(val);
        oh[(size_t)row * cD + d] = h;
        ol[(size_t)row * cD + d] = __float2bfloat16_rn(val - __bfloat162float(h));
    }
}

// combine head-GEMM loss partials -> per-row nll (reads only 8MB + targets)
__global__ void __launch_bounds__(256) loss_combine_kernel(
    const float* __restrict__ logits, const int* __restrict__ tgt,
    float* __restrict__ nll) {
    const int r = blockIdx.x;
    float m = -INFINITY, s = 0.0f;
    for (int t = threadIdx.x; t < cVT; t += 256) {
        float2 p = g_part[(size_t)t * cM + r];
        float nm = fmaxf(m, p.x);
        s = s * __expf(m - nm) + p.y * __expf(p.x - nm);
        m = nm;
    }
    #pragma unroll
    for (int o = 16; o; o >>= 1) {
        float mo = __shfl_xor_sync(0xffffffffu, m, o);
        float so = __shfl_xor_sync(0xffffffffu, s, o);
        float nm = fmaxf(m, mo);
        s = s * __expf(m - nm) + so * __expf(mo - nm);
        m = nm;
    }
    __shared__ float shm[8], shs[8];
    int w = threadIdx.x >> 5, l = threadIdx.x & 31;
    if (l == 0) { shm[w] = m; shs[w] = s; }
    __syncthreads();
    if (w == 0) {
        m = (l < 8) ? shm[l] : -INFINITY;
        s = (l < 8) ? shs[l] : 0.0f;
        #pragma unroll
        for (int o = 4; o; o >>= 1) {
            float mo = __shfl_xor_sync(0xffffffffu, m, o);
            float so = __shfl_xor_sync(0xffffffffu, s, o);
            float nm = fmaxf(m, mo);
            s = s * __expf(m - nm) + so * __expf(mo - nm);
            m = nm;
        }
        if (l == 0)
            nll[r] = -(logits[(size_t)r * cV + tgt[r]] - m - logf(s));
    }
}

__global__ void __launch_bounds__(256) loss_reduce_kernel(const float* __restrict__ nll,
                                                          float* __restrict__ out) {
    float s = 0.0f;
    for (int i = threadIdx.x; i < cM; i += 256) s += nll[i];
    s = blockReduceSum(s);
    if (threadIdx.x == 0) *out = s / (float)cM;
}

// ---------------------------------------------------------------------------
// Launch
// ---------------------------------------------------------------------------
template<typename T> static T* sym(const void* s) {
    void* p; cudaGetSymbolAddress(&p, s); return (T*)p;
}

using bf16 = __nv_bfloat16;

//               NT  BT    BIAS  RES   GELU  WC    WPL   ZM SWAP  LOSSP
#define GQKV  gemm_u<128,true ,false,false,false,false,false,2,false,false>
#define GHEAD gemm_u<128,true ,false,false,false,true ,false,0,true ,true >
#define GPROJ gemm_u<96 ,true ,false,true ,false,true ,false,0,false,false>
#define GFC   gemm_u<128,true ,true ,false,true ,false,true ,0,false,false>
#define GOUT  gemm_u<96 ,true ,true ,true ,false,true ,false,0,false,false>

extern "C" void kernel_launch(void* const* d_in, const int* in_sizes, int n_in,
                              void* d_out, int out_size) {
    const int*   idx    = (const int*)  d_in[0];
    const int*   tgt    = (const int*)  d_in[1];
    const float* wte    = (const float*)d_in[2];
    const float* wpe    = (const float*)d_in[3];
    const float* ln1_g  = (const float*)d_in[4];
    const float* ln1_b  = (const float*)d_in[5];
    const float* w_attn = (const float*)d_in[6];
    const float* w_proj = (const float*)d_in[7];
    const float* ln2_g  = (const float*)d_in[8];
    const float* ln2_b  = (const float*)d_in[9];
    const float* w_fc   = (const float*)d_in[10];
    const float* b_fc   = (const float*)d_in[11];
    const float* w_out  = (const float*)d_in[12];
    const float* b_out  = (const float*)d_in[13];
    const float* lnf_g  = (const float*)d_in[14];
    const float* lnf_b  = (const float*)d_in[15];
    const float* w_head = (const float*)d_in[16];
    float* logits = (float*)d_out;

    float* x   = sym<float>(g_x);
    float* nll = sym<float>(g_nll);
    bf16 *lnh = sym<bf16>(g_ln_h), *lnl = sym<bf16>(g_ln_l);
    bf16 *yh  = sym<bf16>(g_y_h),  *yl  = sym<bf16>(g_y_l);
    bf16 *fch = sym<bf16>(g_fc_h), *fcl = sym<bf16>(g_fc_l);
    bf16 *qh  = sym<bf16>(g_q_h),  *ql  = sym<bf16>(g_q_l);
    bf16 *kh  = sym<bf16>(g_k_h),  *kl  = sym<bf16>(g_k_l);
    bf16 *vh  = sym<bf16>(g_v_h),  *vl  = sym<bf16>(g_v_l);
    bf16 *wah = sym<bf16>(g_wa_h), *wal = sym<bf16>(g_wa_l);
    bf16 *wph = sym<bf16>(g_wp_h), *wpl = sym<bf16>(g_wp_l);
    bf16 *wfh = sym<bf16>(g_wf_h), *wfl = sym<bf16>(g_wf_l);
    bf16 *woh = sym<bf16>(g_wo_h), *wol = sym<bf16>(g_wo_l);
    bf16 *whh = sym<bf16>(g_wh_h), *whl = sym<bf16>(g_wh_l);

    constexpr int SM128T = Geom<128, true>::SMEM;  // 113664
    constexpr int SM96T  = Geom<96,  true>::SMEM;  // 101376

    cudaFuncSetAttribute((const void*)GQKV,  cudaFuncAttributeMaxDynamicSharedMemorySize, SM128T);
    cudaFuncSetAttribute((const void*)GHEAD, cudaFuncAttributeMaxDynamicSharedMemorySize, SM128T);
    cudaFuncSetAttribute((const void*)GPROJ, cudaFuncAttributeMaxDynamicSharedMemorySize, SM96T);
    cudaFuncSetAttribute((const void*)GFC,   cudaFuncAttributeMaxDynamicSharedMemorySize, SM128T);
    cudaFuncSetAttribute((const void*)GOUT,  cudaFuncAttributeMaxDynamicSharedMemorySize, SM96T);
    cudaFuncSetAttribute((const void*)flash_kernel,
                         cudaFuncAttributeMaxDynamicSharedMemorySize, FLASH_SMEM);

    split_kernel<<<cL * cD * cD3 / 1024, 256>>>(w_attn, wah, wal, cL * cD * cD3 / 4);
    split_kernel<<<cL * cD * cD  / 1024, 256>>>(w_proj, wph, wpl, cL * cD * cD  / 4);
    split_kernel<<<cL * cD * cDF / 1024, 256>>>(w_fc,   wfh, wfl, cL * cD * cDF / 4);
    split_kernel<<<cL * cDF * cD / 1024, 256>>>(w_out,  woh, wol, cL * cDF * cD / 4);
    split_kernel<<<cD * cV       / 1024, 256>>>(w_head, whh, whl, cD * cV       / 4);

    embed_kernel<<<(cM * cD) / 256, 256>>>(idx, wte, wpe, x);

    for (int l = 0; l < cL; l++) {
        ln_kernel<<<cM, 256>>>(x, ln1_g + l * cD, ln1_b + l * cD, lnh, lnl);
        GQKV<<<dim3(cD3 / 128, cM / 128, 1), 256, SM128T>>>(
            lnh, lnl, wah + (size_t)l * cD * cD3, wal + (size_t)l * cD * cD3,
            nullptr, nullptr, nullptr, qh, ql, kh, kl, vh, vl, cD3, cD, cD3, 0, 0, 0);
        flash_kernel<<<dim3(cT / 128, cZ), 256, FLASH_SMEM>>>(
            qh, ql, kh, kl, vh, vl, yh, yl);
        GPROJ<<<dim3(cD / 96, cM / 128, 1), 256, SM96T>>>(
            yh, yl, wph + (size_t)l * cD * cD, wpl + (size_t)l * cD * cD,
            nullptr, x, x, nullptr, nullptr, nullptr, nullptr, nullptr, nullptr,
            cD, cD, cD, 0, 0, 0);
        ln_kernel<<<cM, 256>>>(x, ln2_g + l * cD, ln2_b + l * cD, lnh, lnl);
        GFC<<<dim3(cDF / 128, cM / 128, 1), 256, SM128T>>>(
            lnh, lnl, wfh + (size_t)l * cD * cDF, wfl + (size_t)l * cD * cDF,
            b_fc + l * cDF, nullptr, nullptr, fch, fcl, nullptr, nullptr, nullptr, nullptr,
            cDF, cD, cDF, 0, 0, 0);
        GOUT<<<dim3(cD / 96, cM / 128, 1), 256, SM96T>>>(
            fch, fcl, woh + (size_t)l * cDF * cD, wol + (size_t)l * cDF * cD,
            b_out + l * cD, x, x, nullptr, nullptr, nullptr, nullptr, nullptr, nullptr,
            cD, cDF, cD, 0, 0, 0);
    }

    ln_kernel<<<cM, 256>>>(x, lnf_g, lnf_b, lnh, lnl);
    GHEAD<<<dim3(cM / 128, cV / 128, 1), 256, SM128T>>>(
        lnh, lnl, whh, whl, nullptr, nullptr, logits, nullptr, nullptr,
        nullptr, nullptr, nullptr, nullptr, cV, cD, cV, 0, 0, 0);

    if (out_size >= cM * cV + 1) {
        loss_combine_kernel<<<cM, 256>>>(logits, tgt, nll);
        loss_reduce_kernel<<<1, 256>>>(nll, logits + (size_t)cM * cV);
    }
}

// round 13
// speedup vs baseline: 1.0786x; 1.0786x over previous
#include <cuda_runtime.h>
#include <cuda_bf16.h>
#include <math.h>
#include <stdint.h>

// ---------------------------------------------------------------------------
// Problem constants
// ---------------------------------------------------------------------------
constexpr int cV  = 32000;
constexpr int cD  = 768;
constexpr int cH  = 12;
constexpr int cL  = 8;
constexpr int cT  = 1024;
constexpr int cB  = 4;
constexpr int cHD = cD / cH;          // 64
constexpr int cM  = cB * cT;          // 4096
constexpr int cD3 = 3 * cD;           // 2304
constexpr int cDF = 4 * cD;           // 3072
constexpr int cZ  = cB * cH;          // 48 heads
constexpr int cVT = cV / 128;         // 250 head n-tiles
constexpr size_t cQH = (size_t)cT * cHD;       // 65536 per head

// ---------------------------------------------------------------------------
// Scratch (device globals — no allocation allowed)
// ---------------------------------------------------------------------------
__device__ float g_x  [cM * cD];
__device__ float g_nll[cM];
__device__ float2 g_part[(size_t)cVT * cM];    // head loss partials (max,sumexp)

__device__ __nv_bfloat16 g_ln_h[cM * cD],  g_ln_l[cM * cD];
__device__ __nv_bfloat16 g_y_h [cM * cD],  g_y_l [cM * cD];
__device__ __nv_bfloat16 g_fc_h[cM * cDF], g_fc_l[cM * cDF];
__device__ __nv_bfloat16 g_q_h [cZ * cT * cHD], g_q_l [cZ * cT * cHD];
__device__ __nv_bfloat16 g_k_h [cZ * cT * cHD], g_k_l [cZ * cT * cHD];
__device__ __nv_bfloat16 g_v_h [cZ * cT * cHD], g_v_l [cZ * cT * cHD];
__device__ __nv_bfloat16 g_wa_h[cL * cD * cD3], g_wa_l[cL * cD * cD3];
__device__ __nv_bfloat16 g_wp_h[cL * cD * cD],  g_wp_l[cL * cD * cD];
__device__ __nv_bfloat16 g_wf_h[cL * cD * cDF], g_wf_l[cL * cD * cDF];
__device__ __nv_bfloat16 g_wo_h[cL * cDF * cD], g_wo_l[cL * cDF * cD];
__device__ __nv_bfloat16 g_wh_h[cD * cV],       g_wh_l[cD * cV];

// ---------------------------------------------------------------------------
// PTX helpers
// ---------------------------------------------------------------------------
__device__ __forceinline__ void cp_async16(uint32_t saddr, const void* gptr) {
    asm volatile("cp.async.cg.shared.global [%0], [%1], 16;"
                 :: "r"(saddr), "l"(gptr));
}
#define CP_COMMIT() asm volatile("cp.async.commit_group;" ::: "memory")
#define CP_WAIT0()  asm volatile("cp.async.wait_group 0;" ::: "memory")
#define CP_WAIT1()  asm volatile("cp.async.wait_group 1;" ::: "memory")

__device__ __forceinline__ void ldsm_x4(uint32_t* r, uint32_t addr) {
    asm volatile("ldmatrix.sync.aligned.m8n8.x4.shared.b16 {%0,%1,%2,%3}, [%4];"
        : "=r"(r[0]), "=r"(r[1]), "=r"(r[2]), "=r"(r[3]) : "r"(addr));
}
__device__ __forceinline__ void ldsm_x4_t(uint32_t* r, uint32_t addr) {
    asm volatile("ldmatrix.sync.aligned.m8n8.x4.trans.shared.b16 {%0,%1,%2,%3}, [%4];"
        : "=r"(r[0]), "=r"(r[1]), "=r"(r[2]), "=r"(r[3]) : "r"(addr));
}
__device__ __forceinline__ void mma_bf16(float* d, const uint32_t* a,
                                         uint32_t b0, uint32_t b1) {
    asm volatile(
        "mma.sync.aligned.m16n8k16.row.col.f32.bf16.bf16.f32 "
        "{%0,%1,%2,%3},{%4,%5,%6,%7},{%8,%9},{%0,%1,%2,%3};"
        : "+f"(d[0]), "+f"(d[1]), "+f"(d[2]), "+f"(d[3])
        : "r"(a[0]), "r"(a[1]), "r"(a[2]), "r"(a[3]), "r"(b0), "r"(b1));
}

__device__ __forceinline__ uint32_t pack_bf16x2(float lo, float hi) {
    uint32_t d;
    asm("cvt.rn.bf16x2.f32 %0, %1, %2;" : "=r"(d) : "f"(hi), "f"(lo));
    return d;
}
__device__ __forceinline__ void split2(float v0, float v1,
                                       uint32_t& hp, uint32_t& lp) {
    hp = pack_bf16x2(v0, v1);
    float h0 = __uint_as_float(hp << 16);
    float h1 = __uint_as_float(hp & 0xffff0000u);
    lp = pack_bf16x2(v0 - h0, v1 - h1);
}

__device__ __forceinline__ float gelu_exact(float x) {
    return 0.5f * x * (1.0f + erff(x * 0.70710678118654752f));
}

// ---------------------------------------------------------------------------
// Generalized split-bf16 GEMM (3-mma Markidis): C = A @ W(op)
// 3-stage cp.async pipeline, ONE __syncthreads per k-iteration,
// staging at BOTTOM of iteration (Round-9 winning structure).
// LOSSP: fuse per-tile (max, sum-exp) partials into the epilogue (head GEMM).
// ---------------------------------------------------------------------------
template<int NT, bool BTRANS>
struct Geom {
    static constexpr int SBb = BTRANS ? (2 * NT + 16) : 80;
    static constexpr int BSZ = BTRANS ? 32 * SBb : NT * 80;
    static constexpr int AL  = 10240;
    static constexpr int BH  = 20480;
    static constexpr int BL  = BH + BSZ;
    static constexpr int BUF = BH + 2 * BSZ;
    static constexpr int SMEM = 3 * BUF;          // 3 stages
};

template<int NT, bool BTRANS, bool BIAS, bool RES, bool GELU,
         bool WC, bool WPL, int ZMODE, bool SWAPXY, bool LOSSP>
__global__ void __launch_bounds__(256, 2) gemm_u(
    const __nv_bfloat16* __restrict__ Ah, const __nv_bfloat16* __restrict__ Al,
    const __nv_bfloat16* __restrict__ Wh, const __nv_bfloat16* __restrict__ Wl,
    const float* __restrict__ bias, const float* __restrict__ Rres,
    float* __restrict__ C,
    __nv_bfloat16* __restrict__ Ch, __nv_bfloat16* __restrict__ Cl,
    __nv_bfloat16* __restrict__ Dh, __nv_bfloat16* __restrict__ Dl,
    __nv_bfloat16* __restrict__ Eh, __nv_bfloat16* __restrict__ El,
    int N, int K, int ldc, size_t sA, size_t sW, size_t sC) {

    using G = Geom<NT, BTRANS>;
    extern __shared__ char smem[];
    const uint32_t sb = (uint32_t)__cvta_generic_to_shared(smem);

    const int m0 = (SWAPXY ? blockIdx.x : blockIdx.y) * 128;
    const int n0 = (SWAPXY ? blockIdx.y : blockIdx.x) * NT;

    const int z = blockIdx.z;
    Ah += z * sA; Al += z * sA;
    Wh += z * sW; Wl += z * sW;
    const size_t cofs = z * sC;

    const int tid  = threadIdx.x;
    const int lane = tid & 31;
    const int wid  = tid >> 5;
    const int gr   = lane >> 2;
    const int tg   = lane & 3;
    const int mw   = (wid & 3) * 32;
    const int nw   = (wid >> 2) * (NT / 2);
    const int lr   = lane & 7, lt = lane >> 3;

    const uint32_t aoff = (uint32_t)((mw + (lt & 1) * 8 + lr) * 80 + (lt >> 1) * 16);
    uint32_t boff;
    if (BTRANS) boff = (uint32_t)(((lt & 1) * 8 + lr) * G::SBb + (nw + (lt >> 1) * 8) * 2);
    else        boff = (uint32_t)((nw + (lt >> 1) * 8 + lr) * 80 + (lt & 1) * 16);

    constexpr int NTW = NT / 16;
    float acc[2][NTW][4];
    #pragma unroll
    for (int mi = 0; mi < 2; mi++)
        #pragma unroll
        for (int nt = 0; nt < NTW; nt++)
            #pragma unroll
            for (int q = 0; q < 4; q++) acc[mi][nt][q] = 0.0f;

    const int NK = K >> 5;

    auto stage = [&](int ib, int buf) {
        const int k0 = ib << 5;
        const uint32_t bb = sb + buf * G::BUF;
        #pragma unroll
        for (int j = 0; j < 2; j++) {
            int c = tid + 256 * j;
            int row = c >> 2, seg = c & 3;
            uint32_t d = bb + (uint32_t)(row * 80 + seg * 16);
            size_t s = (size_t)(m0 + row) * K + k0 + seg * 8;
            cp_async16(d, Ah + s);
            cp_async16(d + G::AL, Al + s);
        }
        if (BTRANS) {
            constexpr int SEGS = NT / 8;
            constexpr int BCH = 32 * SEGS;
            #pragma unroll
            for (int j = 0; j < (BCH + 255) / 256; j++) {
                int c = tid + 256 * j;
                if ((BCH % 256 == 0) || c < BCH) {
                    int kr = c / SEGS, seg = c - kr * SEGS;
                    uint32_t d = bb + G::BH + (uint32_t)(kr * G::SBb + seg * 16);
                    size_t s = (size_t)(k0 + kr) * N + n0 + seg * 8;
                    cp_async16(d, Wh + s);
                    cp_async16(d + G::BSZ, Wl + s);
                }
            }
        } else {
            constexpr int BCH = NT * 4;
            #pragma unroll
            for (int j = 0; j < (BCH + 255) / 256; j++) {
                int c = tid + 256 * j;
                if ((BCH % 256 == 0) || c < BCH) {
                    int row = c >> 2, seg = c & 3;
                    uint32_t d = bb + G::BH + (uint32_t)(row * 80 + seg * 16);
                    size_t s = (size_t)(n0 + row) * K + k0 + seg * 8;
                    cp_async16(d, Wh + s);
                    cp_async16(d + G::BSZ, Wl + s);
                }
            }
        }
    };

    stage(0, 0); CP_COMMIT();
    stage(1, 1); CP_COMMIT();

    for (int ib = 0; ib < NK; ib++) {
        const int buf = ib % 3;
        CP_WAIT1();
        __syncthreads();

        const uint32_t base = sb + buf * G::BUF;
        const uint32_t aHb = base + aoff;
        const uint32_t aLb = base + G::AL + aoff;
        const uint32_t bHb = base + G::BH + boff;
        const uint32_t bLb = base + G::BL + boff;

        #pragma unroll
        for (int ks = 0; ks < 2; ks++) {
            uint32_t ahi[2][4], alo[2][4];
            ldsm_x4(ahi[0], aHb + ks * 32);
            ldsm_x4(ahi[1], aHb + 1280 + ks * 32);
            ldsm_x4(alo[0], aLb + ks * 32);
            ldsm_x4(alo[1], aLb + 1280 + ks * 32);
            #pragma unroll
            for (int g = 0; g < NT / 32; g++) {
                uint32_t bh[4], bl[4];
                if (BTRANS) {
                    ldsm_x4_t(bh, bHb + ks * (16 * G::SBb) + g * 32);
                    ldsm_x4_t(bl, bLb + ks * (16 * G::SBb) + g * 32);
                } else {
                    ldsm_x4(bh, bHb + ks * 32 + g * 1280);
                    ldsm_x4(bl, bLb + ks * 32 + g * 1280);
                }
                const int nt = g * 2;
                mma_bf16(acc[0][nt],     ahi[0], bh[0], bh[1]);
                mma_bf16(acc[1][nt],     ahi[1], bh[0], bh[1]);
                mma_bf16(acc[0][nt + 1], ahi[0], bh[2], bh[3]);
                mma_bf16(acc[1][nt + 1], ahi[1], bh[2], bh[3]);
                mma_bf16(acc[0][nt],     ahi[0], bl[0], bl[1]);
                mma_bf16(acc[1][nt],     ahi[1], bl[0], bl[1]);
                mma_bf16(acc[0][nt + 1], ahi[0], bl[2], bl[3]);
                mma_bf16(acc[1][nt + 1], ahi[1], bl[2], bl[3]);
                mma_bf16(acc[0][nt],     alo[0], bh[0], bh[1]);
                mma_bf16(acc[1][nt],     alo[1], bh[0], bh[1]);
                mma_bf16(acc[0][nt + 1], alo[0], bh[2], bh[3]);
                mma_bf16(acc[1][nt + 1], alo[1], bh[2], bh[3]);
            }
        }
        // Staging at BOTTOM (Round-9 structure): overlaps the mma tail.
        // Hazard-free without a second barrier: buffer (ib+2)%3 was consumed
        // in iteration ib-1; every warp passed this iteration's __syncthreads.
        if (ib + 2 < NK) stage(ib + 2, (ib + 2) % 3);
        CP_COMMIT();
    }

    #pragma unroll
    for (int mi = 0; mi < 2; mi++) {
        const int r0 = m0 + mw + mi * 16 + gr;
        #pragma unroll
        for (int nt = 0; nt < NTW; nt++) {
            const int c0 = n0 + nw + nt * 8 + tg * 2;
            float2 v0 = make_float2(acc[mi][nt][0], acc[mi][nt][1]);
            float2 v1 = make_float2(acc[mi][nt][2], acc[mi][nt][3]);
            if (BIAS) {
                float2 bv = *(const float2*)(bias + c0);
                v0.x += bv.x; v0.y += bv.y;
                v1.x += bv.x; v1.y += bv.y;
            }
            if (GELU) {
                v0.x = gelu_exact(v0.x); v0.y = gelu_exact(v0.y);
                v1.x = gelu_exact(v1.x); v1.y = gelu_exact(v1.y);
            }
            if (ZMODE == 2) {
                const int sec = n0 / cD;
                const int cc  = c0 - sec * cD;
                const int h   = cc >> 6, d = cc & 63;
                const float scale = (sec == 0) ? 0.125f : 1.0f;
                uint32_t* ph = (uint32_t*)(sec == 0 ? Ch : sec == 1 ? Dh : Eh);
                uint32_t* pl = (uint32_t*)(sec == 0 ? Cl : sec == 1 ? Dl : El);
                const int b = r0 >> 10, t0 = r0 & 1023;
                size_t zb = (size_t)(b * cH + h) * 1024;
                size_t oA = (zb + t0)     * 32 + (d >> 1);
                size_t oB = (zb + t0 + 8) * 32 + (d >> 1);
                uint32_t hp, lp;
                split2(v0.x * scale, v0.y * scale, hp, lp);
                ph[oA] = hp; pl[oA] = lp;
                split2(v1.x * scale, v1.y * scale, hp, lp);
                ph[oB] = hp; pl[oB] = lp;
            } else {
                size_t o0 = cofs + (size_t)r0 * ldc + c0;
                size_t o1 = cofs + (size_t)(r0 + 8) * ldc + c0;
                if (RES) {
                    float2 a0 = *(const float2*)(Rres + o0);
                    float2 a1 = *(const float2*)(Rres + o1);
                    v0.x += a0.x; v0.y += a0.y;
                    v1.x += a1.x; v1.y += a1.y;
                }
                if (WC) {
                    *(float2*)(C + o0) = v0;
                    *(float2*)(C + o1) = v1;
                }
                if (WPL) {
                    uint32_t hp, lp;
                    split2(v0.x, v0.y, hp, lp);
                    ((uint32_t*)Ch)[o0 >> 1] = hp;
                    ((uint32_t*)Cl)[o0 >> 1] = lp;
                    split2(v1.x, v1.y, hp, lp);
                    ((uint32_t*)Ch)[o1 >> 1] = hp;
                    ((uint32_t*)Cl)[o1 >> 1] = lp;
                }
            }
        }
    }

    if (LOSSP) {
        // per-tile (max, sum-exp) partials over this CTA's NT columns.
        float pm[2][2], ps[2][2];
        #pragma unroll
        for (int mi = 0; mi < 2; mi++) {
            #pragma unroll
            for (int rh = 0; rh < 2; rh++) {
                float m = -INFINITY;
                #pragma unroll
                for (int nt = 0; nt < NTW; nt++)
                    m = fmaxf(m, fmaxf(acc[mi][nt][rh * 2], acc[mi][nt][rh * 2 + 1]));
                float s = 0.0f;
                #pragma unroll
                for (int nt = 0; nt < NTW; nt++)
                    s += __expf(acc[mi][nt][rh * 2] - m)
                       + __expf(acc[mi][nt][rh * 2 + 1] - m);
                #pragma unroll
                for (int o = 1; o <= 2; o <<= 1) {
                    float mo = __shfl_xor_sync(0xffffffffu, m, o);
                    float so = __shfl_xor_sync(0xffffffffu, s, o);
                    float nm = fmaxf(m, mo);
                    s = s * __expf(m - nm) + so * __expf(mo - nm);
                    m = nm;
                }
                pm[mi][rh] = m; ps[mi][rh] = s;
            }
        }
        __syncthreads();
        float* sp = (float*)smem;                // [2 halves][128 rows][2]
        if (tg == 0) {
            int half = wid >> 2;
            #pragma unroll
            for (int mi = 0; mi < 2; mi++)
                #pragma unroll
                for (int rh = 0; rh < 2; rh++) {
                    int row = mw + mi * 16 + gr + rh * 8;
                    sp[(half * 128 + row) * 2 + 0] = pm[mi][rh];
                    sp[(half * 128 + row) * 2 + 1] = ps[mi][rh];
                }
        }
        __syncthreads();
        if (tid < 128) {
            float m0v = sp[tid * 2],           s0v = sp[tid * 2 + 1];
            float m1v = sp[(128 + tid) * 2],   s1v = sp[(128 + tid) * 2 + 1];
            float nm = fmaxf(m0v, m1v);
            float sc = s0v * __expf(m0v - nm) + s1v * __expf(m1v - nm);
            g_part[(size_t)(n0 >> 7) * cM + (m0 + tid)] = make_float2(nm, sc);
        }
    }
}

// ---------------------------------------------------------------------------
// Fused flash attention (split-bf16 mma, online softmax)
// ---------------------------------------------------------------------------
constexpr int F_SQ   = 144;
constexpr int F_PL   = 128 * F_SQ;
constexpr int F_KV0  = 2 * F_PL;
constexpr int F_KVSZ = 4 * F_PL;
constexpr int FLASH_SMEM = 2 * F_PL + 2 * F_KVSZ;  // 184320

__global__ void __launch_bounds__(256, 1) flash_kernel(
    const __nv_bfloat16* __restrict__ qh, const __nv_bfloat16* __restrict__ ql,
    const __nv_bfloat16* __restrict__ kh, const __nv_bfloat16* __restrict__ kl,
    const __nv_bfloat16* __restrict__ vh, const __nv_bfloat16* __restrict__ vl,
    __nv_bfloat16* __restrict__ yh, __nv_bfloat16* __restrict__ yl) {

    extern __shared__ char smem[];
    const uint32_t sb = (uint32_t)__cvta_generic_to_shared(smem);
    const int qb = blockIdx.x;
    const int z  = blockIdx.y;
    const int q0 = qb * 128;
    const int tid  = threadIdx.x;
    const int lane = tid & 31;
    const int wid  = tid >> 5;
    const int gr   = lane >> 2;
    const int tg   = lane & 3;
    const int wq   = wid * 16;
    const int lr   = lane & 7, lt = lane >> 3;

    const __nv_bfloat16* qhz = qh + (size_t)z * cQH;
    const __nv_bfloat16* qlz = ql + (size_t)z * cQH;
    const __nv_bfloat16* khz = kh + (size_t)z * cQH;
    const __nv_bfloat16* klz = kl + (size_t)z * cQH;
    const __nv_bfloat16* vhz = vh + (size_t)z * cQH;
    const __nv_bfloat16* vlz = vl + (size_t)z * cQH;

    #pragma unroll
    for (int j = 0; j < 4; j++) {
        int c = tid + 256 * j;
        int row = c >> 3, seg = c & 7;
        uint32_t d = sb + (uint32_t)(row * F_SQ + seg * 16);
        size_t s = (size_t)(q0 + row) * cHD + seg * 8;
        cp_async16(d, qhz + s);
        cp_async16(d + F_PL, qlz + s);
    }
    auto stageKV = [&](int kb, int buf) {
        const uint32_t bb = sb + F_KV0 + buf * F_KVSZ;
        #pragma unroll
        for (int j = 0; j < 4; j++) {
            int c = tid + 256 * j;
            int row = c >> 3, seg = c & 7;
            uint32_t d = bb + (uint32_t)(row * F_SQ + seg * 16);
            size_t s = (size_t)(kb * 128 + row) * cHD + seg * 8;
            cp_async16(d, khz + s);
            cp_async16(d + F_PL, klz + s);
            cp_async16(d + 2 * F_PL, vhz + s);
            cp_async16(d + 3 * F_PL, vlz + s);
        }
    };

    stageKV(0, 0);
    CP_COMMIT();
    if (qb >= 1) { stageKV(1, 1); CP_COMMIT(); }

    float mrow[2] = { -INFINITY, -INFINITY };
    float lrow[2] = { 0.0f, 0.0f };
    float oacc[8][4];
    #pragma unroll
    for (int nt = 0; nt < 8; nt++)
        #pragma unroll
        for (int q = 0; q < 4; q++) oacc[nt][q] = 0.0f;

    uint32_t qfh[4][4], qfl[4][4];
    bool qloaded = false;

    const uint32_t q_aoff = (uint32_t)((wq + (lt & 1) * 8 + lr) * F_SQ + (lt >> 1) * 16);
    const uint32_t k_boff = (uint32_t)(((lt >> 1) * 8 + lr) * F_SQ + (lt & 1) * 16);
    const uint32_t v_boff = (uint32_t)(((lt & 1) * 8 + lr) * F_SQ + (lt >> 1) * 16);

    for (int kb = 0; kb <= qb; kb++) {
        if (kb < qb) { CP_WAIT1(); } else { CP_WAIT0(); }
        __syncthreads();

        if (!qloaded) {
            #pragma unroll
            for (int ks = 0; ks < 4; ks++) {
                ldsm_x4(qfh[ks], sb + q_aoff + ks * 32);
                ldsm_x4(qfl[ks], sb + F_PL + q_aoff + ks * 32);
            }
            qloaded = true;
        }

        const uint32_t kvb = sb + F_KV0 + (kb & 1) * F_KVSZ;

        float s[16][4];
        #pragma unroll
        for (int nt = 0; nt < 16; nt++)
            #pragma unroll
            for (int q = 0; q < 4; q++) s[nt][q] = 0.0f;

        #pragma unroll
        for (int ks = 0; ks < 4; ks++) {
            #pragma unroll
            for (int g = 0; g < 8; g++) {
                uint32_t bh[4], bl[4];
                uint32_t addr = kvb + k_boff + (uint32_t)(g * 16 * F_SQ) + ks * 32;
                ldsm_x4(bh, addr);
                ldsm_x4(bl, addr + F_PL);
                const int nt = g * 2;
                mma_bf16(s[nt],     qfh[ks], bh[0], bh[1]);
                mma_bf16(s[nt + 1], qfh[ks], bh[2], bh[3]);
                mma_bf16(s[nt],     qfh[ks], bl[0], bl[1]);
                mma_bf16(s[nt + 1], qfh[ks], bl[2], bl[3]);
                mma_bf16(s[nt],     qfl[ks], bh[0], bh[1]);
                mma_bf16(s[nt + 1], qfl[ks], bh[2], bh[3]);
            }
        }

        if (kb == qb) {
            const int r0 = wq + gr, r1 = wq + gr + 8;
            #pragma unroll
            for (int nt = 0; nt < 16; nt++) {
                const int c0 = nt * 8 + tg * 2;
                if (c0     > r0) s[nt][0] = -1e30f;
                if (c0 + 1 > r0) s[nt][1] = -1e30f;
                if (c0     > r1) s[nt][2] = -1e30f;
                if (c0 + 1 > r1) s[nt][3] = -1e30f;
            }
        }

        float mn0 = -INFINITY, mn1 = -INFINITY;
        #pragma unroll
        for (int nt = 0; nt < 16; nt++) {
            mn0 = fmaxf(mn0, fmaxf(s[nt][0], s[nt][1]));
            mn1 = fmaxf(mn1, fmaxf(s[nt][2], s[nt][3]));
        }
        mn0 = fmaxf(mn0, __shfl_xor_sync(0xffffffffu, mn0, 1));
        mn0 = fmaxf(mn0, __shfl_xor_sync(0xffffffffu, mn0, 2));
        mn1 = fmaxf(mn1, __shfl_xor_sync(0xffffffffu, mn1, 1));
        mn1 = fmaxf(mn1, __shfl_xor_sync(0xffffffffu, mn1, 2));
        float mnew0 = fmaxf(mrow[0], mn0);
        float mnew1 = fmaxf(mrow[1], mn1);
        float al0 = __expf(mrow[0] - mnew0);
        float al1 = __expf(mrow[1] - mnew1);
        mrow[0] = mnew0; mrow[1] = mnew1;

        float rs0 = 0.0f, rs1 = 0.0f;
        #pragma unroll
        for (int nt = 0; nt < 16; nt++) {
            s[nt][0] = __expf(s[nt][0] - mnew0);
            s[nt][1] = __expf(s[nt][1] - mnew0);
            s[nt][2] = __expf(s[nt][2] - mnew1);
            s[nt][3] = __expf(s[nt][3] - mnew1);
            rs0 += s[nt][0] + s[nt][1];
            rs1 += s[nt][2] + s[nt][3];
        }
        rs0 += __shfl_xor_sync(0xffffffffu, rs0, 1);
        rs0 += __shfl_xor_sync(0xffffffffu, rs0, 2);
        rs1 += __shfl_xor_sync(0xffffffffu, rs1, 1);
        rs1 += __shfl_xor_sync(0xffffffffu, rs1, 2);
        lrow[0] = lrow[0] * al0 + rs0;
        lrow[1] = lrow[1] * al1 + rs1;

        #pragma unroll
        for (int nt = 0; nt < 8; nt++) {
            oacc[nt][0] *= al0; oacc[nt][1] *= al0;
            oacc[nt][2] *= al1; oacc[nt][3] *= al1;
        }

        #pragma unroll
        for (int ks = 0; ks < 8; ks++) {
            uint32_t pah[4], pal[4];
            uint32_t h0, l0;
            split2(s[2*ks][0],   s[2*ks][1],   h0, l0); pah[0] = h0; pal[0] = l0;
            split2(s[2*ks][2],   s[2*ks][3],   h0, l0); pah[1] = h0; pal[1] = l0;
            split2(s[2*ks+1][0], s[2*ks+1][1], h0, l0); pah[2] = h0; pal[2] = l0;
            split2(s[2*ks+1][2], s[2*ks+1][3], h0, l0); pah[3] = h0; pal[3] = l0;
            #pragma unroll
            for (int g = 0; g < 4; g++) {
                uint32_t bvh[4], bvl[4];
                uint32_t addr = kvb + 2 * F_PL + v_boff
                              + (uint32_t)(ks * 16 * F_SQ) + g * 32;
                ldsm_x4_t(bvh, addr);
                ldsm_x4_t(bvl, addr + F_PL);
                const int nt = g * 2;
                mma_bf16(oacc[nt],     pah, bvh[0], bvh[1]);
                mma_bf16(oacc[nt + 1], pah, bvh[2], bvh[3]);
                mma_bf16(oacc[nt],     pah, bvl[0], bvl[1]);
                mma_bf16(oacc[nt + 1], pah, bvl[2], bvl[3]);
                mma_bf16(oacc[nt],     pal, bvh[0], bvh[1]);
                mma_bf16(oacc[nt + 1], pal, bvh[2], bvh[3]);
            }
        }

        __syncthreads();
        if (kb + 2 <= qb) { stageKV(kb + 2, kb & 1); CP_COMMIT(); }
    }

    const float inv0 = 1.0f / lrow[0];
    const float inv1 = 1.0f / lrow[1];
    const int b = z / cH, h = z % cH;
    const int r0 = b * cT + q0 + wq + gr;
    #pragma unroll
    for (int nt = 0; nt < 8; nt++) {
        const int c0 = h * cHD + nt * 8 + tg * 2;
        uint32_t hp, lp;
        split2(oacc[nt][0] * inv0, oacc[nt][1] * inv0, hp, lp);
        size_t o0 = ((size_t)r0 * cD + c0) >> 1;
        ((uint32_t*)yh)[o0] = hp; ((uint32_t*)yl)[o0] = lp;
        split2(oacc[nt][2] * inv1, oacc[nt][3] * inv1, hp, lp);
        size_t o1 = ((size_t)(r0 + 8) * cD + c0) >> 1;
        ((uint32_t*)yh)[o1] = hp; ((uint32_t*)yl)[o1] = lp;
    }
}

// ---------------------------------------------------------------------------
// Block reductions (blockDim.x == 256)
// ---------------------------------------------------------------------------
__device__ __forceinline__ float blockReduceSum(float v) {
    __shared__ float sh[8];
    #pragma unroll
    for (int o = 16; o; o >>= 1) v += __shfl_xor_sync(0xffffffffu, v, o);
    int w = threadIdx.x >> 5, l = threadIdx.x & 31;
    __syncthreads();
    if (l == 0) sh[w] = v;
    __syncthreads();
    if (w == 0) {
        v = (l < 8) ? sh[l] : 0.0f;
        #pragma unroll
        for (int o = 16; o; o >>= 1) v += __shfl_xor_sync(0xffffffffu, v, o);
        if (l == 0) sh[0] = v;
    }
    __syncthreads();
    return sh[0];
}

// ---------------------------------------------------------------------------
// Small kernels
// ---------------------------------------------------------------------------
__global__ void __launch_bounds__(256) split_kernel(const float* __restrict__ src,
                                                    __nv_bfloat16* __restrict__ hi,
                                                    __nv_bfloat16* __restrict__ lo,
                                                    int nquads) {
    int i = blockIdx.x * blockDim.x + threadIdx.x;
    if (i >= nquads) return;
    float4 v = *(const float4*)(src + (size_t)i * 4);
    uint32_t h0, l0, h1, l1;
    split2(v.x, v.y, h0, l0);
    split2(v.z, v.w, h1, l1);
    ((uint2*)hi)[i] = make_uint2(h0, h1);
    ((uint2*)lo)[i] = make_uint2(l0, l1);
}

__global__ void embed_kernel(const int* __restrict__ idx,
                             const float* __restrict__ wte,
                             const float* __restrict__ wpe,
                             float* __restrict__ x) {
    int i = blockIdx.x * blockDim.x + threadIdx.x;
    int row = i / cD;
    int d   = i - row * cD;
    int t   = row & (cT - 1);
    int tok = idx[row];
    x[i] = wte[(size_t)tok * cD + d] + wpe[(size_t)t * cD + d];
}

__global__ void __launch_bounds__(256) ln_kernel(const float* __restrict__ x,
                                                 const float* __restrict__ g,
                                                 const float* __restrict__ b,
                                                 __nv_bfloat16* __restrict__ oh,
                                                 __nv_bfloat16* __restrict__ ol) {
    const int row = blockIdx.x;
    const float* xr = x + (size_t)row * cD;
    const int t = threadIdx.x;
    float v0 = xr[t], v1 = xr[t + 256], v2 = xr[t + 512];
    float s  = blockReduceSum(v0 + v1 + v2);
    float s2 = blockReduceSum(v0 * v0 + v1 * v1 + v2 * v2);
    const float inv = 1.0f / cD;
    float mu  = s * inv;
    float var = s2 * inv - mu * mu;
    float rs  = rsqrtf(var + 1e-5f);
    #pragma unroll
    for (int j = 0; j < 3; j++) {
        int d = t + j * 256;
        float val = (((j == 0) ? v0 : (j == 1) ? v1 : v2) - mu) * rs * g[d] + b[d];
        __nv_bfloat16 h = __float2bfloat16_rn(val);
        oh[(size_t)row * cD + d] = h;
        ol[(size_t)row * cD + d] = __float2bfloat16_rn(val - __bfloat162float(h));
    }
}

// combine head-GEMM loss partials -> per-row nll (reads only 8MB + targets)
__global__ void __launch_bounds__(256) loss_combine_kernel(
    const float* __restrict__ logits, const int* __restrict__ tgt,
    float* __restrict__ nll) {
    const int r = blockIdx.x;
    float m = -INFINITY, s = 0.0f;
    for (int t = threadIdx.x; t < cVT; t += 256) {
        float2 p = g_part[(size_t)t * cM + r];
        float nm = fmaxf(m, p.x);
        s = s * __expf(m - nm) + p.y * __expf(p.x - nm);
        m = nm;
    }
    #pragma unroll
    for (int o = 16; o; o >>= 1) {
        float mo = __shfl_xor_sync(0xffffffffu, m, o);
        float so = __shfl_xor_sync(0xffffffffu, s, o);
        float nm = fmaxf(m, mo);
        s = s * __expf(m - nm) + so * __expf(mo - nm);
        m = nm;
    }
    __shared__ float shm[8], shs[8];
    int w = threadIdx.x >> 5, l = threadIdx.x & 31;
    if (l == 0) { shm[w] = m; shs[w] = s; }
    __syncthreads();
    if (w == 0) {
        m = (l < 8) ? shm[l] : -INFINITY;
        s = (l < 8) ? shs[l] : 0.0f;
        #pragma unroll
        for (int o = 4; o; o >>= 1) {
            float mo = __shfl_xor_sync(0xffffffffu, m, o);
            float so = __shfl_xor_sync(0xffffffffu, s, o);
            float nm = fmaxf(m, mo);
            s = s * __expf(m - nm) + so * __expf(mo - nm);
            m = nm;
        }
        if (l == 0)
            nll[r] = -(logits[(size_t)r * cV + tgt[r]] - m - logf(s));
    }
}

__global__ void __launch_bounds__(256) loss_reduce_kernel(const float* __restrict__ nll,
                                                          float* __restrict__ out) {
    float s = 0.0f;
    for (int i = threadIdx.x; i < cM; i += 256) s += nll[i];
    s = blockReduceSum(s);
    if (threadIdx.x == 0) *out = s / (float)cM;
}

// ---------------------------------------------------------------------------
// Launch
// ---------------------------------------------------------------------------
template<typename T> static T* sym(const void* s) {
    void* p; cudaGetSymbolAddress(&p, s); return (T*)p;
}

using bf16 = __nv_bfloat16;

//               NT  BT    BIAS  RES   GELU  WC    WPL   ZM SWAP  LOSSP
#define GQKV  gemm_u<128,true ,false,false,false,false,false,2,false,false>
#define GHEAD gemm_u<128,true ,false,false,false,true ,false,0,true ,true >
#define GPROJ gemm_u<96 ,true ,false,true ,false,true ,false,0,false,false>
#define GFC   gemm_u<128,true ,true ,false,true ,false,true ,0,false,false>
#define GOUT  gemm_u<96 ,true ,true ,true ,false,true ,false,0,false,false>

extern "C" void kernel_launch(void* const* d_in, const int* in_sizes, int n_in,
                              void* d_out, int out_size) {
    const int*   idx    = (const int*)  d_in[0];
    const int*   tgt    = (const int*)  d_in[1];
    const float* wte    = (const float*)d_in[2];
    const float* wpe    = (const float*)d_in[3];
    const float* ln1_g  = (const float*)d_in[4];
    const float* ln1_b  = (const float*)d_in[5];
    const float* w_attn = (const float*)d_in[6];
    const float* w_proj = (const float*)d_in[7];
    const float* ln2_g  = (const float*)d_in[8];
    const float* ln2_b  = (const float*)d_in[9];
    const float* w_fc   = (const float*)d_in[10];
    const float* b_fc   = (const float*)d_in[11];
    const float* w_out  = (const float*)d_in[12];
    const float* b_out  = (const float*)d_in[13];
    const float* lnf_g  = (const float*)d_in[14];
    const float* lnf_b  = (const float*)d_in[15];
    const float* w_head = (const float*)d_in[16];
    float* logits = (float*)d_out;

    float* x   = sym<float>(g_x);
    float* nll = sym<float>(g_nll);
    bf16 *lnh = sym<bf16>(g_ln_h), *lnl = sym<bf16>(g_ln_l);
    bf16 *yh  = sym<bf16>(g_y_h),  *yl  = sym<bf16>(g_y_l);
    bf16 *fch = sym<bf16>(g_fc_h), *fcl = sym<bf16>(g_fc_l);
    bf16 *qh  = sym<bf16>(g_q_h),  *ql  = sym<bf16>(g_q_l);
    bf16 *kh  = sym<bf16>(g_k_h),  *kl  = sym<bf16>(g_k_l);
    bf16 *vh  = sym<bf16>(g_v_h),  *vl  = sym<bf16>(g_v_l);
    bf16 *wah = sym<bf16>(g_wa_h), *wal = sym<bf16>(g_wa_l);
    bf16 *wph = sym<bf16>(g_wp_h), *wpl = sym<bf16>(g_wp_l);
    bf16 *wfh = sym<bf16>(g_wf_h), *wfl = sym<bf16>(g_wf_l);
    bf16 *woh = sym<bf16>(g_wo_h), *wol = sym<bf16>(g_wo_l);
    bf16 *whh = sym<bf16>(g_wh_h), *whl = sym<bf16>(g_wh_l);

    constexpr int SM128T = Geom<128, true>::SMEM;  // 113664
    constexpr int SM96T  = Geom<96,  true>::SMEM;  // 101376

    cudaFuncSetAttribute((const void*)GQKV,  cudaFuncAttributeMaxDynamicSharedMemorySize, SM128T);
    cudaFuncSetAttribute((const void*)GHEAD, cudaFuncAttributeMaxDynamicSharedMemorySize, SM128T);
    cudaFuncSetAttribute((const void*)GPROJ, cudaFuncAttributeMaxDynamicSharedMemorySize, SM96T);
    cudaFuncSetAttribute((const void*)GFC,   cudaFuncAttributeMaxDynamicSharedMemorySize, SM128T);
    cudaFuncSetAttribute((const void*)GOUT,  cudaFuncAttributeMaxDynamicSharedMemorySize, SM96T);
    cudaFuncSetAttribute((const void*)flash_kernel,
                         cudaFuncAttributeMaxDynamicSharedMemorySize, FLASH_SMEM);

    split_kernel<<<cL * cD * cD3 / 1024, 256>>>(w_attn, wah, wal, cL * cD * cD3 / 4);
    split_kernel<<<cL * cD * cD  / 1024, 256>>>(w_proj, wph, wpl, cL * cD * cD  / 4);
    split_kernel<<<cL * cD * cDF / 1024, 256>>>(w_fc,   wfh, wfl, cL * cD * cDF / 4);
    split_kernel<<<cL * cDF * cD / 1024, 256>>>(w_out,  woh, wol, cL * cDF * cD / 4);
    split_kernel<<<cD * cV       / 1024, 256>>>(w_head, whh, whl, cD * cV       / 4);

    embed_kernel<<<(cM * cD) / 256, 256>>>(idx, wte, wpe, x);

    for (int l = 0; l < cL; l++) {
        ln_kernel<<<cM, 256>>>(x, ln1_g + l * cD, ln1_b + l * cD, lnh, lnl);
        GQKV<<<dim3(cD3 / 128, cM / 128, 1), 256, SM128T>>>(
            lnh, lnl, wah + (size_t)l * cD * cD3, wal + (size_t)l * cD * cD3,
            nullptr, nullptr, nullptr, qh, ql, kh, kl, vh, vl, cD3, cD, cD3, 0, 0, 0);
        flash_kernel<<<dim3(cT / 128, cZ), 256, FLASH_SMEM>>>(
            qh, ql, kh, kl, vh, vl, yh, yl);
        GPROJ<<<dim3(cD / 96, cM / 128, 1), 256, SM96T>>>(
            yh, yl, wph + (size_t)l * cD * cD, wpl + (size_t)l * cD * cD,
            nullptr, x, x, nullptr, nullptr, nullptr, nullptr, nullptr, nullptr,
            cD, cD, cD, 0, 0, 0);
        ln_kernel<<<cM, 256>>>(x, ln2_g + l * cD, ln2_b + l * cD, lnh, lnl);
        GFC<<<dim3(cDF / 128, cM / 128, 1), 256, SM128T>>>(
            lnh, lnl, wfh + (size_t)l * cD * cDF, wfl + (size_t)l * cD * cDF,
            b_fc + l * cDF, nullptr, nullptr, fch, fcl, nullptr, nullptr, nullptr, nullptr,
            cDF, cD, cDF, 0, 0, 0);
        GOUT<<<dim3(cD / 96, cM / 128, 1), 256, SM96T>>>(
            fch, fcl, woh + (size_t)l * cDF * cD, wol + (size_t)l * cDF * cD,
            b_out + l * cD, x, x, nullptr, nullptr, nullptr, nullptr, nullptr, nullptr,
            cD, cDF, cD, 0, 0, 0);
    }

    ln_kernel<<<cM, 256>>>(x, lnf_g, lnf_b, lnh, lnl);
    GHEAD<<<dim3(cM / 128, cV / 128, 1), 256, SM128T>>>(
        lnh, lnl, whh, whl, nullptr, nullptr, logits, nullptr, nullptr,
        nullptr, nullptr, nullptr, nullptr, cV, cD, cV, 0, 0, 0);

    if (out_size >= cM * cV + 1) {
        loss_combine_kernel<<<cM, 256>>>(logits, tgt, nll);
        loss_reduce_kernel<<<1, 256>>>(nll, logits + (size_t)cM * cV);
    }
}

// round 14
// speedup vs baseline: 1.0837x; 1.0047x over previous
#include <cuda_runtime.h>
#include <cuda_bf16.h>
#include <math.h>
#include <stdint.h>

// ---------------------------------------------------------------------------
// Problem constants
// ---------------------------------------------------------------------------
constexpr int cV  = 32000;
constexpr int cD  = 768;
constexpr int cH  = 12;
constexpr int cL  = 8;
constexpr int cT  = 1024;
constexpr int cB  = 4;
constexpr int cHD = cD / cH;          // 64
constexpr int cM  = cB * cT;          // 4096
constexpr int cD3 = 3 * cD;           // 2304
constexpr int cDF = 4 * cD;           // 3072
constexpr int cZ  = cB * cH;          // 48 heads
constexpr int cVT = cV / 128;         // 250 head n-tiles
constexpr size_t cQH = (size_t)cT * cHD;       // 65536 per head

// split_all segment boundaries (in 16B quads)
constexpr size_t SQ0 = (size_t)cL * cD * cD3 / 4;          // 3538944
constexpr size_t SQ1 = SQ0 + (size_t)cL * cD * cD  / 4;    // 4718592
constexpr size_t SQ2 = SQ1 + (size_t)cL * cD * cDF / 4;    // 9437184
constexpr size_t SQ3 = SQ2 + (size_t)cL * cDF * cD / 4;    // 14155776
constexpr size_t SQ4 = SQ3 + (size_t)cD * cV       / 4;    // 20299776

// ---------------------------------------------------------------------------
// Scratch (device globals — no allocation allowed)
// ---------------------------------------------------------------------------
__device__ float g_x  [cM * cD];
__device__ float g_nll[cM];
__device__ float2 g_part[(size_t)cVT * cM];    // head loss partials (max,sumexp)

__device__ __nv_bfloat16 g_ln_h[cM * cD],  g_ln_l[cM * cD];
__device__ __nv_bfloat16 g_y_h [cM * cD],  g_y_l [cM * cD];
__device__ __nv_bfloat16 g_fc_h[cM * cDF], g_fc_l[cM * cDF];
__device__ __nv_bfloat16 g_q_h [cZ * cT * cHD], g_q_l [cZ * cT * cHD];
__device__ __nv_bfloat16 g_k_h [cZ * cT * cHD], g_k_l [cZ * cT * cHD];
__device__ __nv_bfloat16 g_v_h [cZ * cT * cHD], g_v_l [cZ * cT * cHD];
__device__ __nv_bfloat16 g_wa_h[cL * cD * cD3], g_wa_l[cL * cD * cD3];
__device__ __nv_bfloat16 g_wp_h[cL * cD * cD],  g_wp_l[cL * cD * cD];
__device__ __nv_bfloat16 g_wf_h[cL * cD * cDF], g_wf_l[cL * cD * cDF];
__device__ __nv_bfloat16 g_wo_h[cL * cDF * cD], g_wo_l[cL * cDF * cD];
__device__ __nv_bfloat16 g_wh_h[cD * cV],       g_wh_l[cD * cV];

// ---------------------------------------------------------------------------
// PTX helpers
// ---------------------------------------------------------------------------
__device__ __forceinline__ void cp_async16(uint32_t saddr, const void* gptr) {
    asm volatile("cp.async.cg.shared.global [%0], [%1], 16;"
                 :: "r"(saddr), "l"(gptr));
}
#define CP_COMMIT() asm volatile("cp.async.commit_group;" ::: "memory")
#define CP_WAIT0()  asm volatile("cp.async.wait_group 0;" ::: "memory")
#define CP_WAIT1()  asm volatile("cp.async.wait_group 1;" ::: "memory")

__device__ __forceinline__ void ldsm_x4(uint32_t* r, uint32_t addr) {
    asm volatile("ldmatrix.sync.aligned.m8n8.x4.shared.b16 {%0,%1,%2,%3}, [%4];"
        : "=r"(r[0]), "=r"(r[1]), "=r"(r[2]), "=r"(r[3]) : "r"(addr));
}
__device__ __forceinline__ void ldsm_x4_t(uint32_t* r, uint32_t addr) {
    asm volatile("ldmatrix.sync.aligned.m8n8.x4.trans.shared.b16 {%0,%1,%2,%3}, [%4];"
        : "=r"(r[0]), "=r"(r[1]), "=r"(r[2]), "=r"(r[3]) : "r"(addr));
}
__device__ __forceinline__ void mma_bf16(float* d, const uint32_t* a,
                                         uint32_t b0, uint32_t b1) {
    asm volatile(
        "mma.sync.aligned.m16n8k16.row.col.f32.bf16.bf16.f32 "
        "{%0,%1,%2,%3},{%4,%5,%6,%7},{%8,%9},{%0,%1,%2,%3};"
        : "+f"(d[0]), "+f"(d[1]), "+f"(d[2]), "+f"(d[3])
        : "r"(a[0]), "r"(a[1]), "r"(a[2]), "r"(a[3]), "r"(b0), "r"(b1));
}

__device__ __forceinline__ uint32_t pack_bf16x2(float lo, float hi) {
    uint32_t d;
    asm("cvt.rn.bf16x2.f32 %0, %1, %2;" : "=r"(d) : "f"(hi), "f"(lo));
    return d;
}
__device__ __forceinline__ void split2(float v0, float v1,
                                       uint32_t& hp, uint32_t& lp) {
    hp = pack_bf16x2(v0, v1);
    float h0 = __uint_as_float(hp << 16);
    float h1 = __uint_as_float(hp & 0xffff0000u);
    lp = pack_bf16x2(v0 - h0, v1 - h1);
}

__device__ __forceinline__ float gelu_exact(float x) {
    return 0.5f * x * (1.0f + erff(x * 0.70710678118654752f));
}

// ---------------------------------------------------------------------------
// Generalized split-bf16 GEMM (3-mma Markidis): C = A @ W(op)
// 3-stage cp.async pipeline, ONE __syncthreads per k-iteration,
// staging at BOTTOM of iteration (validated best placement).
// LOSSP: fuse per-tile (max, sum-exp) partials into the epilogue (head GEMM).
// ---------------------------------------------------------------------------
template<int NT, bool BTRANS>
struct Geom {
    static constexpr int SBb = BTRANS ? (2 * NT + 16) : 80;
    static constexpr int BSZ = BTRANS ? 32 * SBb : NT * 80;
    static constexpr int AL  = 10240;
    static constexpr int BH  = 20480;
    static constexpr int BL  = BH + BSZ;
    static constexpr int BUF = BH + 2 * BSZ;
    static constexpr int SMEM = 3 * BUF;          // 3 stages
};

template<int NT, bool BTRANS, bool BIAS, bool RES, bool GELU,
         bool WC, bool WPL, int ZMODE, bool SWAPXY, bool LOSSP>
__global__ void __launch_bounds__(256, 2) gemm_u(
    const __nv_bfloat16* __restrict__ Ah, const __nv_bfloat16* __restrict__ Al,
    const __nv_bfloat16* __restrict__ Wh, const __nv_bfloat16* __restrict__ Wl,
    const float* __restrict__ bias, const float* __restrict__ Rres,
    float* __restrict__ C,
    __nv_bfloat16* __restrict__ Ch, __nv_bfloat16* __restrict__ Cl,
    __nv_bfloat16* __restrict__ Dh, __nv_bfloat16* __restrict__ Dl,
    __nv_bfloat16* __restrict__ Eh, __nv_bfloat16* __restrict__ El,
    int N, int K, int ldc, size_t sA, size_t sW, size_t sC) {

    using G = Geom<NT, BTRANS>;
    extern __shared__ char smem[];
    const uint32_t sb = (uint32_t)__cvta_generic_to_shared(smem);

    const int m0 = (SWAPXY ? blockIdx.x : blockIdx.y) * 128;
    const int n0 = (SWAPXY ? blockIdx.y : blockIdx.x) * NT;

    const int z = blockIdx.z;
    Ah += z * sA; Al += z * sA;
    Wh += z * sW; Wl += z * sW;
    const size_t cofs = z * sC;

    const int tid  = threadIdx.x;
    const int lane = tid & 31;
    const int wid  = tid >> 5;
    const int gr   = lane >> 2;
    const int tg   = lane & 3;
    const int mw   = (wid & 3) * 32;
    const int nw   = (wid >> 2) * (NT / 2);
    const int lr   = lane & 7, lt = lane >> 3;

    const uint32_t aoff = (uint32_t)((mw + (lt & 1) * 8 + lr) * 80 + (lt >> 1) * 16);
    uint32_t boff;
    if (BTRANS) boff = (uint32_t)(((lt & 1) * 8 + lr) * G::SBb + (nw + (lt >> 1) * 8) * 2);
    else        boff = (uint32_t)((nw + (lt >> 1) * 8 + lr) * 80 + (lt & 1) * 16);

    constexpr int NTW = NT / 16;
    float acc[2][NTW][4];
    #pragma unroll
    for (int mi = 0; mi < 2; mi++)
        #pragma unroll
        for (int nt = 0; nt < NTW; nt++)
            #pragma unroll
            for (int q = 0; q < 4; q++) acc[mi][nt][q] = 0.0f;

    const int NK = K >> 5;

    auto stage = [&](int ib, int buf) {
        const int k0 = ib << 5;
        const uint32_t bb = sb + buf * G::BUF;
        #pragma unroll
        for (int j = 0; j < 2; j++) {
            int c = tid + 256 * j;
            int row = c >> 2, seg = c & 3;
            uint32_t d = bb + (uint32_t)(row * 80 + seg * 16);
            size_t s = (size_t)(m0 + row) * K + k0 + seg * 8;
            cp_async16(d, Ah + s);
            cp_async16(d + G::AL, Al + s);
        }
        if (BTRANS) {
            constexpr int SEGS = NT / 8;
            constexpr int BCH = 32 * SEGS;
            #pragma unroll
            for (int j = 0; j < (BCH + 255) / 256; j++) {
                int c = tid + 256 * j;
                if ((BCH % 256 == 0) || c < BCH) {
                    int kr = c / SEGS, seg = c - kr * SEGS;
                    uint32_t d = bb + G::BH + (uint32_t)(kr * G::SBb + seg * 16);
                    size_t s = (size_t)(k0 + kr) * N + n0 + seg * 8;
                    cp_async16(d, Wh + s);
                    cp_async16(d + G::BSZ, Wl + s);
                }
            }
        } else {
            constexpr int BCH = NT * 4;
            #pragma unroll
            for (int j = 0; j < (BCH + 255) / 256; j++) {
                int c = tid + 256 * j;
                if ((BCH % 256 == 0) || c < BCH) {
                    int row = c >> 2, seg = c & 3;
                    uint32_t d = bb + G::BH + (uint32_t)(row * 80 + seg * 16);
                    size_t s = (size_t)(n0 + row) * K + k0 + seg * 8;
                    cp_async16(d, Wh + s);
                    cp_async16(d + G::BSZ, Wl + s);
                }
            }
        }
    };

    stage(0, 0); CP_COMMIT();
    stage(1, 1); CP_COMMIT();

    for (int ib = 0; ib < NK; ib++) {
        const int buf = ib % 3;
        CP_WAIT1();
        __syncthreads();

        const uint32_t base = sb + buf * G::BUF;
        const uint32_t aHb = base + aoff;
        const uint32_t aLb = base + G::AL + aoff;
        const uint32_t bHb = base + G::BH + boff;
        const uint32_t bLb = base + G::BL + boff;

        #pragma unroll
        for (int ks = 0; ks < 2; ks++) {
            uint32_t ahi[2][4], alo[2][4];
            ldsm_x4(ahi[0], aHb + ks * 32);
            ldsm_x4(ahi[1], aHb + 1280 + ks * 32);
            ldsm_x4(alo[0], aLb + ks * 32);
            ldsm_x4(alo[1], aLb + 1280 + ks * 32);
            #pragma unroll
            for (int g = 0; g < NT / 32; g++) {
                uint32_t bh[4], bl[4];
                if (BTRANS) {
                    ldsm_x4_t(bh, bHb + ks * (16 * G::SBb) + g * 32);
                    ldsm_x4_t(bl, bLb + ks * (16 * G::SBb) + g * 32);
                } else {
                    ldsm_x4(bh, bHb + ks * 32 + g * 1280);
                    ldsm_x4(bl, bLb + ks * 32 + g * 1280);
                }
                const int nt = g * 2;
                mma_bf16(acc[0][nt],     ahi[0], bh[0], bh[1]);
                mma_bf16(acc[1][nt],     ahi[1], bh[0], bh[1]);
                mma_bf16(acc[0][nt + 1], ahi[0], bh[2], bh[3]);
                mma_bf16(acc[1][nt + 1], ahi[1], bh[2], bh[3]);
                mma_bf16(acc[0][nt],     ahi[0], bl[0], bl[1]);
                mma_bf16(acc[1][nt],     ahi[1], bl[0], bl[1]);
                mma_bf16(acc[0][nt + 1], ahi[0], bl[2], bl[3]);
                mma_bf16(acc[1][nt + 1], ahi[1], bl[2], bl[3]);
                mma_bf16(acc[0][nt],     alo[0], bh[0], bh[1]);
                mma_bf16(acc[1][nt],     alo[1], bh[0], bh[1]);
                mma_bf16(acc[0][nt + 1], alo[0], bh[2], bh[3]);
                mma_bf16(acc[1][nt + 1], alo[1], bh[2], bh[3]);
            }
        }
        // Staging at BOTTOM: overlaps the mma tail. Hazard-free without a
        // second barrier: buffer (ib+2)%3 was consumed in iteration ib-1;
        // every warp passed this iteration's __syncthreads.
        if (ib + 2 < NK) stage(ib + 2, (ib + 2) % 3);
        CP_COMMIT();
    }

    #pragma unroll
    for (int mi = 0; mi < 2; mi++) {
        const int r0 = m0 + mw + mi * 16 + gr;
        #pragma unroll
        for (int nt = 0; nt < NTW; nt++) {
            const int c0 = n0 + nw + nt * 8 + tg * 2;
            float2 v0 = make_float2(acc[mi][nt][0], acc[mi][nt][1]);
            float2 v1 = make_float2(acc[mi][nt][2], acc[mi][nt][3]);
            if (BIAS) {
                float2 bv = *(const float2*)(bias + c0);
                v0.x += bv.x; v0.y += bv.y;
                v1.x += bv.x; v1.y += bv.y;
            }
            if (GELU) {
                v0.x = gelu_exact(v0.x); v0.y = gelu_exact(v0.y);
                v1.x = gelu_exact(v1.x); v1.y = gelu_exact(v1.y);
            }
            if (ZMODE == 2) {
                const int sec = n0 / cD;
                const int cc  = c0 - sec * cD;
                const int h   = cc >> 6, d = cc & 63;
                const float scale = (sec == 0) ? 0.125f : 1.0f;
                uint32_t* ph = (uint32_t*)(sec == 0 ? Ch : sec == 1 ? Dh : Eh);
                uint32_t* pl = (uint32_t*)(sec == 0 ? Cl : sec == 1 ? Dl : El);
                const int b = r0 >> 10, t0 = r0 & 1023;
                size_t zb = (size_t)(b * cH + h) * 1024;
                size_t oA = (zb + t0)     * 32 + (d >> 1);
                size_t oB = (zb + t0 + 8) * 32 + (d >> 1);
                uint32_t hp, lp;
                split2(v0.x * scale, v0.y * scale, hp, lp);
                ph[oA] = hp; pl[oA] = lp;
                split2(v1.x * scale, v1.y * scale, hp, lp);
                ph[oB] = hp; pl[oB] = lp;
            } else {
                size_t o0 = cofs + (size_t)r0 * ldc + c0;
                size_t o1 = cofs + (size_t)(r0 + 8) * ldc + c0;
                if (RES) {
                    float2 a0 = *(const float2*)(Rres + o0);
                    float2 a1 = *(const float2*)(Rres + o1);
                    v0.x += a0.x; v0.y += a0.y;
                    v1.x += a1.x; v1.y += a1.y;
                }
                if (WC) {
                    *(float2*)(C + o0) = v0;
                    *(float2*)(C + o1) = v1;
                }
                if (WPL) {
                    uint32_t hp, lp;
                    split2(v0.x, v0.y, hp, lp);
                    ((uint32_t*)Ch)[o0 >> 1] = hp;
                    ((uint32_t*)Cl)[o0 >> 1] = lp;
                    split2(v1.x, v1.y, hp, lp);
                    ((uint32_t*)Ch)[o1 >> 1] = hp;
                    ((uint32_t*)Cl)[o1 >> 1] = lp;
                }
            }
        }
    }

    if (LOSSP) {
        // per-tile (max, sum-exp) partials over this CTA's NT columns.
        float pm[2][2], ps[2][2];
        #pragma unroll
        for (int mi = 0; mi < 2; mi++) {
            #pragma unroll
            for (int rh = 0; rh < 2; rh++) {
                float m = -INFINITY;
                #pragma unroll
                for (int nt = 0; nt < NTW; nt++)
                    m = fmaxf(m, fmaxf(acc[mi][nt][rh * 2], acc[mi][nt][rh * 2 + 1]));
                float s = 0.0f;
                #pragma unroll
                for (int nt = 0; nt < NTW; nt++)
                    s += __expf(acc[mi][nt][rh * 2] - m)
                       + __expf(acc[mi][nt][rh * 2 + 1] - m);
                #pragma unroll
                for (int o = 1; o <= 2; o <<= 1) {
                    float mo = __shfl_xor_sync(0xffffffffu, m, o);
                    float so = __shfl_xor_sync(0xffffffffu, s, o);
                    float nm = fmaxf(m, mo);
                    s = s * __expf(m - nm) + so * __expf(mo - nm);
                    m = nm;
                }
                pm[mi][rh] = m; ps[mi][rh] = s;
            }
        }
        __syncthreads();
        float* sp = (float*)smem;                // [2 halves][128 rows][2]
        if (tg == 0) {
            int half = wid >> 2;
            #pragma unroll
            for (int mi = 0; mi < 2; mi++)
                #pragma unroll
                for (int rh = 0; rh < 2; rh++) {
                    int row = mw + mi * 16 + gr + rh * 8;
                    sp[(half * 128 + row) * 2 + 0] = pm[mi][rh];
                    sp[(half * 128 + row) * 2 + 1] = ps[mi][rh];
                }
        }
        __syncthreads();
        if (tid < 128) {
            float m0v = sp[tid * 2],           s0v = sp[tid * 2 + 1];
            float m1v = sp[(128 + tid) * 2],   s1v = sp[(128 + tid) * 2 + 1];
            float nm = fmaxf(m0v, m1v);
            float sc = s0v * __expf(m0v - nm) + s1v * __expf(m1v - nm);
            g_part[(size_t)(n0 >> 7) * cM + (m0 + tid)] = make_float2(nm, sc);
        }
    }
}

// ---------------------------------------------------------------------------
// Fused flash attention (split-bf16 mma, online softmax)
// ---------------------------------------------------------------------------
constexpr int F_SQ   = 144;
constexpr int F_PL   = 128 * F_SQ;
constexpr int F_KV0  = 2 * F_PL;
constexpr int F_KVSZ = 4 * F_PL;
constexpr int FLASH_SMEM = 2 * F_PL + 2 * F_KVSZ;  // 184320

__global__ void __launch_bounds__(256, 1) flash_kernel(
    const __nv_bfloat16* __restrict__ qh, const __nv_bfloat16* __restrict__ ql,
    const __nv_bfloat16* __restrict__ kh, const __nv_bfloat16* __restrict__ kl,
    const __nv_bfloat16* __restrict__ vh, const __nv_bfloat16* __restrict__ vl,
    __nv_bfloat16* __restrict__ yh, __nv_bfloat16* __restrict__ yl) {

    extern __shared__ char smem[];
    const uint32_t sb = (uint32_t)__cvta_generic_to_shared(smem);
    const int qb = blockIdx.x;
    const int z  = blockIdx.y;
    const int q0 = qb * 128;
    const int tid  = threadIdx.x;
    const int lane = tid & 31;
    const int wid  = tid >> 5;
    const int gr   = lane >> 2;
    const int tg   = lane & 3;
    const int wq   = wid * 16;
    const int lr   = lane & 7, lt = lane >> 3;

    const __nv_bfloat16* qhz = qh + (size_t)z * cQH;
    const __nv_bfloat16* qlz = ql + (size_t)z * cQH;
    const __nv_bfloat16* khz = kh + (size_t)z * cQH;
    const __nv_bfloat16* klz = kl + (size_t)z * cQH;
    const __nv_bfloat16* vhz = vh + (size_t)z * cQH;
    const __nv_bfloat16* vlz = vl + (size_t)z * cQH;

    #pragma unroll
    for (int j = 0; j < 4; j++) {
        int c = tid + 256 * j;
        int row = c >> 3, seg = c & 7;
        uint32_t d = sb + (uint32_t)(row * F_SQ + seg * 16);
        size_t s = (size_t)(q0 + row) * cHD + seg * 8;
        cp_async16(d, qhz + s);
        cp_async16(d + F_PL, qlz + s);
    }
    auto stageKV = [&](int kb, int buf) {
        const uint32_t bb = sb + F_KV0 + buf * F_KVSZ;
        #pragma unroll
        for (int j = 0; j < 4; j++) {
            int c = tid + 256 * j;
            int row = c >> 3, seg = c & 7;
            uint32_t d = bb + (uint32_t)(row * F_SQ + seg * 16);
            size_t s = (size_t)(kb * 128 + row) * cHD + seg * 8;
            cp_async16(d, khz + s);
            cp_async16(d + F_PL, klz + s);
            cp_async16(d + 2 * F_PL, vhz + s);
            cp_async16(d + 3 * F_PL, vlz + s);
        }
    };

    stageKV(0, 0);
    CP_COMMIT();
    if (qb >= 1) { stageKV(1, 1); CP_COMMIT(); }

    float mrow[2] = { -INFINITY, -INFINITY };
    float lrow[2] = { 0.0f, 0.0f };
    float oacc[8][4];
    #pragma unroll
    for (int nt = 0; nt < 8; nt++)
        #pragma unroll
        for (int q = 0; q < 4; q++) oacc[nt][q] = 0.0f;

    uint32_t qfh[4][4], qfl[4][4];
    bool qloaded = false;

    const uint32_t q_aoff = (uint32_t)((wq + (lt & 1) * 8 + lr) * F_SQ + (lt >> 1) * 16);
    const uint32_t k_boff = (uint32_t)(((lt >> 1) * 8 + lr) * F_SQ + (lt & 1) * 16);
    const uint32_t v_boff = (uint32_t)(((lt & 1) * 8 + lr) * F_SQ + (lt >> 1) * 16);

    for (int kb = 0; kb <= qb; kb++) {
        if (kb < qb) { CP_WAIT1(); } else { CP_WAIT0(); }
        __syncthreads();

        if (!qloaded) {
            #pragma unroll
            for (int ks = 0; ks < 4; ks++) {
                ldsm_x4(qfh[ks], sb + q_aoff + ks * 32);
                ldsm_x4(qfl[ks], sb + F_PL + q_aoff + ks * 32);
            }
            qloaded = true;
        }

        const uint32_t kvb = sb + F_KV0 + (kb & 1) * F_KVSZ;

        float s[16][4];
        #pragma unroll
        for (int nt = 0; nt < 16; nt++)
            #pragma unroll
            for (int q = 0; q < 4; q++) s[nt][q] = 0.0f;

        #pragma unroll
        for (int ks = 0; ks < 4; ks++) {
            #pragma unroll
            for (int g = 0; g < 8; g++) {
                uint32_t bh[4], bl[4];
                uint32_t addr = kvb + k_boff + (uint32_t)(g * 16 * F_SQ) + ks * 32;
                ldsm_x4(bh, addr);
                ldsm_x4(bl, addr + F_PL);
                const int nt = g * 2;
                mma_bf16(s[nt],     qfh[ks], bh[0], bh[1]);
                mma_bf16(s[nt + 1], qfh[ks], bh[2], bh[3]);
                mma_bf16(s[nt],     qfh[ks], bl[0], bl[1]);
                mma_bf16(s[nt + 1], qfh[ks], bl[2], bl[3]);
                mma_bf16(s[nt],     qfl[ks], bh[0], bh[1]);
                mma_bf16(s[nt + 1], qfl[ks], bh[2], bh[3]);
            }
        }

        if (kb == qb) {
            const int r0 = wq + gr, r1 = wq + gr + 8;
            #pragma unroll
            for (int nt = 0; nt < 16; nt++) {
                const int c0 = nt * 8 + tg * 2;
                if (c0     > r0) s[nt][0] = -1e30f;
                if (c0 + 1 > r0) s[nt][1] = -1e30f;
                if (c0     > r1) s[nt][2] = -1e30f;
                if (c0 + 1 > r1) s[nt][3] = -1e30f;
            }
        }

        float mn0 = -INFINITY, mn1 = -INFINITY;
        #pragma unroll
        for (int nt = 0; nt < 16; nt++) {
            mn0 = fmaxf(mn0, fmaxf(s[nt][0], s[nt][1]));
            mn1 = fmaxf(mn1, fmaxf(s[nt][2], s[nt][3]));
        }
        mn0 = fmaxf(mn0, __shfl_xor_sync(0xffffffffu, mn0, 1));
        mn0 = fmaxf(mn0, __shfl_xor_sync(0xffffffffu, mn0, 2));
        mn1 = fmaxf(mn1, __shfl_xor_sync(0xffffffffu, mn1, 1));
        mn1 = fmaxf(mn1, __shfl_xor_sync(0xffffffffu, mn1, 2));
        float mnew0 = fmaxf(mrow[0], mn0);
        float mnew1 = fmaxf(mrow[1], mn1);
        float al0 = __expf(mrow[0] - mnew0);
        float al1 = __expf(mrow[1] - mnew1);
        mrow[0] = mnew0; mrow[1] = mnew1;

        float rs0 = 0.0f, rs1 = 0.0f;
        #pragma unroll
        for (int nt = 0; nt < 16; nt++) {
            s[nt][0] = __expf(s[nt][0] - mnew0);
            s[nt][1] = __expf(s[nt][1] - mnew0);
            s[nt][2] = __expf(s[nt][2] - mnew1);
            s[nt][3] = __expf(s[nt][3] - mnew1);
            rs0 += s[nt][0] + s[nt][1];
            rs1 += s[nt][2] + s[nt][3];
        }
        rs0 += __shfl_xor_sync(0xffffffffu, rs0, 1);
        rs0 += __shfl_xor_sync(0xffffffffu, rs0, 2);
        rs1 += __shfl_xor_sync(0xffffffffu, rs1, 1);
        rs1 += __shfl_xor_sync(0xffffffffu, rs1, 2);
        lrow[0] = lrow[0] * al0 + rs0;
        lrow[1] = lrow[1] * al1 + rs1;

        #pragma unroll
        for (int nt = 0; nt < 8; nt++) {
            oacc[nt][0] *= al0; oacc[nt][1] *= al0;
            oacc[nt][2] *= al1; oacc[nt][3] *= al1;
        }

        #pragma unroll
        for (int ks = 0; ks < 8; ks++) {
            uint32_t pah[4], pal[4];
            uint32_t h0, l0;
            split2(s[2*ks][0],   s[2*ks][1],   h0, l0); pah[0] = h0; pal[0] = l0;
            split2(s[2*ks][2],   s[2*ks][3],   h0, l0); pah[1] = h0; pal[1] = l0;
            split2(s[2*ks+1][0], s[2*ks+1][1], h0, l0); pah[2] = h0; pal[2] = l0;
            split2(s[2*ks+1][2], s[2*ks+1][3], h0, l0); pah[3] = h0; pal[3] = l0;
            #pragma unroll
            for (int g = 0; g < 4; g++) {
                uint32_t bvh[4], bvl[4];
                uint32_t addr = kvb + 2 * F_PL + v_boff
                              + (uint32_t)(ks * 16 * F_SQ) + g * 32;
                ldsm_x4_t(bvh, addr);
                ldsm_x4_t(bvl, addr + F_PL);
                const int nt = g * 2;
                mma_bf16(oacc[nt],     pah, bvh[0], bvh[1]);
                mma_bf16(oacc[nt + 1], pah, bvh[2], bvh[3]);
                mma_bf16(oacc[nt],     pah, bvl[0], bvl[1]);
                mma_bf16(oacc[nt + 1], pah, bvl[2], bvl[3]);
                mma_bf16(oacc[nt],     pal, bvh[0], bvh[1]);
                mma_bf16(oacc[nt + 1], pal, bvh[2], bvh[3]);
            }
        }

        __syncthreads();
        if (kb + 2 <= qb) { stageKV(kb + 2, kb & 1); CP_COMMIT(); }
    }

    const float inv0 = 1.0f / lrow[0];
    const float inv1 = 1.0f / lrow[1];
    const int b = z / cH, h = z % cH;
    const int r0 = b * cT + q0 + wq + gr;
    #pragma unroll
    for (int nt = 0; nt < 8; nt++) {
        const int c0 = h * cHD + nt * 8 + tg * 2;
        uint32_t hp, lp;
        split2(oacc[nt][0] * inv0, oacc[nt][1] * inv0, hp, lp);
        size_t o0 = ((size_t)r0 * cD + c0) >> 1;
        ((uint32_t*)yh)[o0] = hp; ((uint32_t*)yl)[o0] = lp;
        split2(oacc[nt][2] * inv1, oacc[nt][3] * inv1, hp, lp);
        size_t o1 = ((size_t)(r0 + 8) * cD + c0) >> 1;
        ((uint32_t*)yh)[o1] = hp; ((uint32_t*)yl)[o1] = lp;
    }
}

// ---------------------------------------------------------------------------
// Block reductions (blockDim.x == 256)
// ---------------------------------------------------------------------------
__device__ __forceinline__ float blockReduceSum(float v) {
    __shared__ float sh[8];
    #pragma unroll
    for (int o = 16; o; o >>= 1) v += __shfl_xor_sync(0xffffffffu, v, o);
    int w = threadIdx.x >> 5, l = threadIdx.x & 31;
    __syncthreads();
    if (l == 0) sh[w] = v;
    __syncthreads();
    if (w == 0) {
        v = (l < 8) ? sh[l] : 0.0f;
        #pragma unroll
        for (int o = 16; o; o >>= 1) v += __shfl_xor_sync(0xffffffffu, v, o);
        if (l == 0) sh[0] = v;
    }
    __syncthreads();
    return sh[0];
}

// ---------------------------------------------------------------------------
// Small kernels
// ---------------------------------------------------------------------------
// Merged weight splitter: all 5 weight tensors in ONE launch (2 quads/thread).
// Segment boundaries are even, so a thread's quad pair never straddles.
__global__ void __launch_bounds__(256) split_all_kernel(
    const float* __restrict__ wa, const float* __restrict__ wp,
    const float* __restrict__ wf, const float* __restrict__ wo,
    const float* __restrict__ wh,
    __nv_bfloat16* wah, __nv_bfloat16* wal,
    __nv_bfloat16* wph, __nv_bfloat16* wpl,
    __nv_bfloat16* wfh, __nv_bfloat16* wfl,
    __nv_bfloat16* woh, __nv_bfloat16* wol,
    __nv_bfloat16* whh, __nv_bfloat16* whl) {
    size_t q = ((size_t)blockIdx.x * 256 + threadIdx.x) * 2;
    const float* src; __nv_bfloat16 *hi, *lo; size_t base;
    if (q < SQ0)      { src = wa; hi = wah; lo = wal; base = 0;   }
    else if (q < SQ1) { src = wp; hi = wph; lo = wpl; base = SQ0; }
    else if (q < SQ2) { src = wf; hi = wfh; lo = wfl; base = SQ1; }
    else if (q < SQ3) { src = wo; hi = woh; lo = wol; base = SQ2; }
    else              { src = wh; hi = whh; lo = whl; base = SQ3; }
    size_t lq = q - base;
    #pragma unroll
    for (int j = 0; j < 2; j++) {
        float4 v = *(const float4*)(src + (lq + j) * 4);
        uint32_t h0, l0, h1, l1;
        split2(v.x, v.y, h0, l0);
        split2(v.z, v.w, h1, l1);
        ((uint2*)hi)[lq + j] = make_uint2(h0, h1);
        ((uint2*)lo)[lq + j] = make_uint2(l0, l1);
    }
}

// Fused embedding + layer-0 LN1: writes residual x AND LN bf16 planes.
__global__ void __launch_bounds__(256) embed_ln_kernel(
    const int* __restrict__ idx,
    const float* __restrict__ wte, const float* __restrict__ wpe,
    const float* __restrict__ g, const float* __restrict__ b,
    float* __restrict__ x,
    __nv_bfloat16* __restrict__ oh, __nv_bfloat16* __restrict__ ol) {
    const int row = blockIdx.x;
    const int t = threadIdx.x;
    const int tok = idx[row];
    const int tp  = row & (cT - 1);
    float v0 = wte[(size_t)tok * cD + t]       + wpe[(size_t)tp * cD + t];
    float v1 = wte[(size_t)tok * cD + t + 256] + wpe[(size_t)tp * cD + t + 256];
    float v2 = wte[(size_t)tok * cD + t + 512] + wpe[(size_t)tp * cD + t + 512];
    float* xr = x + (size_t)row * cD;
    xr[t] = v0; xr[t + 256] = v1; xr[t + 512] = v2;
    float s  = blockReduceSum(v0 + v1 + v2);
    float s2 = blockReduceSum(v0 * v0 + v1 * v1 + v2 * v2);
    const float inv = 1.0f / cD;
    float mu  = s * inv;
    float var = s2 * inv - mu * mu;
    float rs  = rsqrtf(var + 1e-5f);
    #pragma unroll
    for (int j = 0; j < 3; j++) {
        int d = t + j * 256;
        float val = (((j == 0) ? v0 : (j == 1) ? v1 : v2) - mu) * rs * g[d] + b[d];
        __nv_bfloat16 h = __float2bfloat16_rn(val);
        oh[(size_t)row * cD + d] = h;
        ol[(size_t)row * cD + d] = __float2bfloat16_rn(val - __bfloat162float(h));
    }
}

__global__ void __launch_bounds__(256) ln_kernel(const float* __restrict__ x,
                                                 const float* __restrict__ g,
                                                 const float* __restrict__ b,
                                                 __nv_bfloat16* __restrict__ oh,
                                                 __nv_bfloat16* __restrict__ ol) {
    const int row = blockIdx.x;
    const float* xr = x + (size_t)row * cD;
    const int t = threadIdx.x;
    float v0 = xr[t], v1 = xr[t + 256], v2 = xr[t + 512];
    float s  = blockReduceSum(v0 + v1 + v2);
    float s2 = blockReduceSum(v0 * v0 + v1 * v1 + v2 * v2);
    const float inv = 1.0f / cD;
    float mu  = s * inv;
    float var = s2 * inv - mu * mu;
    float rs  = rsqrtf(var + 1e-5f);
    #pragma unroll
    for (int j = 0; j < 3; j++) {
        int d = t + j * 256;
        float val = (((j == 0) ? v0 : (j == 1) ? v1 : v2) - mu) * rs * g[d] + b[d];
        __nv_bfloat16 h = __float2bfloat16_rn(val);
        oh[(size_t)row * cD + d] = h;
        ol[(size_t)row * cD + d] = __float2bfloat16_rn(val - __bfloat162float(h));
    }
}

// combine head-GEMM loss partials -> per-row nll (reads only 8MB + targets)
__global__ void __launch_bounds__(256) loss_combine_kernel(
    const float* __restrict__ logits, const int* __restrict__ tgt,
    float* __restrict__ nll) {
    const int r = blockIdx.x;
    float m = -INFINITY, s = 0.0f;
    for (int t = threadIdx.x; t < cVT; t += 256) {
        float2 p = g_part[(size_t)t * cM + r];
        float nm = fmaxf(m, p.x);
        s = s * __expf(m - nm) + p.y * __expf(p.x - nm);
        m = nm;
    }
    #pragma unroll
    for (int o = 16; o; o >>= 1) {
        float mo = __shfl_xor_sync(0xffffffffu, m, o);
        float so = __shfl_xor_sync(0xffffffffu, s, o);
        float nm = fmaxf(m, mo);
        s = s * __expf(m - nm) + so * __expf(mo - nm);
        m = nm;
    }
    __shared__ float shm[8], shs[8];
    int w = threadIdx.x >> 5, l = threadIdx.x & 31;
    if (l == 0) { shm[w] = m; shs[w] = s; }
    __syncthreads();
    if (w == 0) {
        m = (l < 8) ? shm[l] : -INFINITY;
        s = (l < 8) ? shs[l] : 0.0f;
        #pragma unroll
        for (int o = 4; o; o >>= 1) {
            float mo = __shfl_xor_sync(0xffffffffu, m, o);
            float so = __shfl_xor_sync(0xffffffffu, s, o);
            float nm = fmaxf(m, mo);
            s = s * __expf(m - nm) + so * __expf(mo - nm);
            m = nm;
        }
        if (l == 0)
            nll[r] = -(logits[(size_t)r * cV + tgt[r]] - m - logf(s));
    }
}

__global__ void __launch_bounds__(256) loss_reduce_kernel(const float* __restrict__ nll,
                                                          float* __restrict__ out) {
    float s = 0.0f;
    for (int i = threadIdx.x; i < cM; i += 256) s += nll[i];
    s = blockReduceSum(s);
    if (threadIdx.x == 0) *out = s / (float)cM;
}

// ---------------------------------------------------------------------------
// Launch
// ---------------------------------------------------------------------------
template<typename T> static T* sym(const void* s) {
    void* p; cudaGetSymbolAddress(&p, s); return (T*)p;
}

using bf16 = __nv_bfloat16;

//               NT  BT    BIAS  RES   GELU  WC    WPL   ZM SWAP  LOSSP
#define GQKV  gemm_u<128,true ,false,false,false,false,false,2,false,false>
#define GHEAD gemm_u<128,true ,false,false,false,true ,false,0,true ,true >
#define GPROJ gemm_u<96 ,true ,false,true ,false,true ,false,0,false,false>
#define GFC   gemm_u<128,true ,true ,false,true ,false,true ,0,false,false>
#define GOUT  gemm_u<96 ,true ,true ,true ,false,true ,false,0,false,false>

extern "C" void kernel_launch(void* const* d_in, const int* in_sizes, int n_in,
                              void* d_out, int out_size) {
    const int*   idx    = (const int*)  d_in[0];
    const int*   tgt    = (const int*)  d_in[1];
    const float* wte    = (const float*)d_in[2];
    const float* wpe    = (const float*)d_in[3];
    const float* ln1_g  = (const float*)d_in[4];
    const float* ln1_b  = (const float*)d_in[5];
    const float* w_attn = (const float*)d_in[6];
    const float* w_proj = (const float*)d_in[7];
    const float* ln2_g  = (const float*)d_in[8];
    const float* ln2_b  = (const float*)d_in[9];
    const float* w_fc   = (const float*)d_in[10];
    const float* b_fc   = (const float*)d_in[11];
    const float* w_out  = (const float*)d_in[12];
    const float* b_out  = (const float*)d_in[13];
    const float* lnf_g  = (const float*)d_in[14];
    const float* lnf_b  = (const float*)d_in[15];
    const float* w_head = (const float*)d_in[16];
    float* logits = (float*)d_out;

    float* x   = sym<float>(g_x);
    float* nll = sym<float>(g_nll);
    bf16 *lnh = sym<bf16>(g_ln_h), *lnl = sym<bf16>(g_ln_l);
    bf16 *yh  = sym<bf16>(g_y_h),  *yl  = sym<bf16>(g_y_l);
    bf16 *fch = sym<bf16>(g_fc_h), *fcl = sym<bf16>(g_fc_l);
    bf16 *qh  = sym<bf16>(g_q_h),  *ql  = sym<bf16>(g_q_l);
    bf16 *kh  = sym<bf16>(g_k_h),  *kl  = sym<bf16>(g_k_l);
    bf16 *vh  = sym<bf16>(g_v_h),  *vl  = sym<bf16>(g_v_l);
    bf16 *wah = sym<bf16>(g_wa_h), *wal = sym<bf16>(g_wa_l);
    bf16 *wph = sym<bf16>(g_wp_h), *wpl = sym<bf16>(g_wp_l);
    bf16 *wfh = sym<bf16>(g_wf_h), *wfl = sym<bf16>(g_wf_l);
    bf16 *woh = sym<bf16>(g_wo_h), *wol = sym<bf16>(g_wo_l);
    bf16 *whh = sym<bf16>(g_wh_h), *whl = sym<bf16>(g_wh_l);

    constexpr int SM128T = Geom<128, true>::SMEM;  // 113664
    constexpr int SM96T  = Geom<96,  true>::SMEM;  // 101376

    cudaFuncSetAttribute((const void*)GQKV,  cudaFuncAttributeMaxDynamicSharedMemorySize, SM128T);
    cudaFuncSetAttribute((const void*)GHEAD, cudaFuncAttributeMaxDynamicSharedMemorySize, SM128T);
    cudaFuncSetAttribute((const void*)GPROJ, cudaFuncAttributeMaxDynamicSharedMemorySize, SM96T);
    cudaFuncSetAttribute((const void*)GFC,   cudaFuncAttributeMaxDynamicSharedMemorySize, SM128T);
    cudaFuncSetAttribute((const void*)GOUT,  cudaFuncAttributeMaxDynamicSharedMemorySize, SM96T);
    cudaFuncSetAttribute((const void*)flash_kernel,
                         cudaFuncAttributeMaxDynamicSharedMemorySize, FLASH_SMEM);

    // one merged weight-split launch (launch idx 0)
    split_all_kernel<<<(int)(SQ4 / 512), 256>>>(
        w_attn, w_proj, w_fc, w_out, w_head,
        wah, wal, wph, wpl, wfh, wfl, woh, wol, whh, whl);

    // fused embedding + layer-0 LN1 (launch idx 1) -> GQKV is launch idx 2
    embed_ln_kernel<<<cM, 256>>>(idx, wte, wpe, ln1_g, ln1_b, x, lnh, lnl);

    for (int l = 0; l < cL; l++) {
        if (l > 0)
            ln_kernel<<<cM, 256>>>(x, ln1_g + l * cD, ln1_b + l * cD, lnh, lnl);
        GQKV<<<dim3(cD3 / 128, cM / 128, 1), 256, SM128T>>>(
            lnh, lnl, wah + (size_t)l * cD * cD3, wal + (size_t)l * cD * cD3,
            nullptr, nullptr, nullptr, qh, ql, kh, kl, vh, vl, cD3, cD, cD3, 0, 0, 0);
        flash_kernel<<<dim3(cT / 128, cZ), 256, FLASH_SMEM>>>(
            qh, ql, kh, kl, vh, vl, yh, yl);
        GPROJ<<<dim3(cD / 96, cM / 128, 1), 256, SM96T>>>(
            yh, yl, wph + (size_t)l * cD * cD, wpl + (size_t)l * cD * cD,
            nullptr, x, x, nullptr, nullptr, nullptr, nullptr, nullptr, nullptr,
            cD, cD, cD, 0, 0, 0);
        ln_kernel<<<cM, 256>>>(x, ln2_g + l * cD, ln2_b + l * cD, lnh, lnl);
        GFC<<<dim3(cDF / 128, cM / 128, 1), 256, SM128T>>>(
            lnh, lnl, wfh + (size_t)l * cD * cDF, wfl + (size_t)l * cD * cDF,
            b_fc + l * cDF, nullptr, nullptr, fch, fcl, nullptr, nullptr, nullptr, nullptr,
            cDF, cD, cDF, 0, 0, 0);
        GOUT<<<dim3(cD / 96, cM / 128, 1), 256, SM96T>>>(
            fch, fcl, woh + (size_t)l * cDF * cD, wol + (size_t)l * cDF * cD,
            b_out + l * cD, x, x, nullptr, nullptr, nullptr, nullptr, nullptr, nullptr,
            cD, cDF, cD, 0, 0, 0);
    }

    ln_kernel<<<cM, 256>>>(x, lnf_g, lnf_b, lnh, lnl);
    GHEAD<<<dim3(cM / 128, cV / 128, 1), 256, SM128T>>>(
        lnh, lnl, whh, whl, nullptr, nullptr, logits, nullptr, nullptr,
        nullptr, nullptr, nullptr, nullptr, cV, cD, cV, 0, 0, 0);

    if (out_size >= cM * cV + 1) {
        loss_combine_kernel<<<cM, 256>>>(logits, tgt, nll);
        loss_reduce_kernel<<<1, 256>>>(nll, logits + (size_t)cM * cV);
    }
}

// round 15
// speedup vs baseline: 1.1115x; 1.0257x over previous
#include <cuda_runtime.h>
#include <cuda_bf16.h>
#include <math.h>
#include <stdint.h>

// ---------------------------------------------------------------------------
// Problem constants
// ---------------------------------------------------------------------------
constexpr int cV  = 32000;
constexpr int cD  = 768;
constexpr int cH  = 12;
constexpr int cL  = 8;
constexpr int cT  = 1024;
constexpr int cB  = 4;
constexpr int cHD = cD / cH;          // 64
constexpr int cM  = cB * cT;          // 4096
constexpr int cD3 = 3 * cD;           // 2304
constexpr int cDF = 4 * cD;           // 3072
constexpr int cZ  = cB * cH;          // 48 heads
constexpr int cVT = cV / 128;         // 250 head n-tiles
constexpr size_t cQH = (size_t)cT * cHD;       // 65536 per head

// split_all segment boundaries (in 16B quads)
constexpr size_t SQ0 = (size_t)cL * cD * cD3 / 4;          // 3538944
constexpr size_t SQ1 = SQ0 + (size_t)cL * cD * cD  / 4;    // 4718592
constexpr size_t SQ2 = SQ1 + (size_t)cL * cD * cDF / 4;    // 9437184
constexpr size_t SQ3 = SQ2 + (size_t)cL * cDF * cD / 4;    // 14155776
constexpr size_t SQ4 = SQ3 + (size_t)cD * cV       / 4;    // 20299776

// ---------------------------------------------------------------------------
// Scratch (device globals — no allocation allowed)
// ---------------------------------------------------------------------------
__device__ float g_x  [cM * cD];
__device__ float g_nll[cM];
__device__ float2 g_part[(size_t)cVT * cM];    // head loss partials (max,sumexp)

__device__ __nv_bfloat16 g_ln_h[cM * cD],  g_ln_l[cM * cD];
__device__ __nv_bfloat16 g_y_h [cM * cD],  g_y_l [cM * cD];
__device__ __nv_bfloat16 g_fc_h[cM * cDF], g_fc_l[cM * cDF];
__device__ __nv_bfloat16 g_q_h [cZ * cT * cHD], g_q_l [cZ * cT * cHD];
__device__ __nv_bfloat16 g_k_h [cZ * cT * cHD], g_k_l [cZ * cT * cHD];
__device__ __nv_bfloat16 g_v_h [cZ * cT * cHD], g_v_l [cZ * cT * cHD];
__device__ __nv_bfloat16 g_wa_h[cL * cD * cD3], g_wa_l[cL * cD * cD3];
__device__ __nv_bfloat16 g_wp_h[cL * cD * cD],  g_wp_l[cL * cD * cD];
__device__ __nv_bfloat16 g_wf_h[cL * cD * cDF], g_wf_l[cL * cD * cDF];
__device__ __nv_bfloat16 g_wo_h[cL * cDF * cD], g_wo_l[cL * cDF * cD];
__device__ __nv_bfloat16 g_wh_h[cD * cV],       g_wh_l[cD * cV];

// ---------------------------------------------------------------------------
// PTX helpers
// ---------------------------------------------------------------------------
__device__ __forceinline__ void cp_async16(uint32_t saddr, const void* gptr) {
    asm volatile("cp.async.cg.shared.global [%0], [%1], 16;"
                 :: "r"(saddr), "l"(gptr));
}
#define CP_COMMIT() asm volatile("cp.async.commit_group;" ::: "memory")
#define CP_WAIT0()  asm volatile("cp.async.wait_group 0;" ::: "memory")
#define CP_WAIT1()  asm volatile("cp.async.wait_group 1;" ::: "memory")

__device__ __forceinline__ void ldsm_x4(uint32_t* r, uint32_t addr) {
    asm volatile("ldmatrix.sync.aligned.m8n8.x4.shared.b16 {%0,%1,%2,%3}, [%4];"
        : "=r"(r[0]), "=r"(r[1]), "=r"(r[2]), "=r"(r[3]) : "r"(addr));
}
__device__ __forceinline__ void ldsm_x4_t(uint32_t* r, uint32_t addr) {
    asm volatile("ldmatrix.sync.aligned.m8n8.x4.trans.shared.b16 {%0,%1,%2,%3}, [%4];"
        : "=r"(r[0]), "=r"(r[1]), "=r"(r[2]), "=r"(r[3]) : "r"(addr));
}
__device__ __forceinline__ void mma_bf16(float* d, const uint32_t* a,
                                         uint32_t b0, uint32_t b1) {
    asm volatile(
        "mma.sync.aligned.m16n8k16.row.col.f32.bf16.bf16.f32 "
        "{%0,%1,%2,%3},{%4,%5,%6,%7},{%8,%9},{%0,%1,%2,%3};"
        : "+f"(d[0]), "+f"(d[1]), "+f"(d[2]), "+f"(d[3])
        : "r"(a[0]), "r"(a[1]), "r"(a[2]), "r"(a[3]), "r"(b0), "r"(b1));
}

__device__ __forceinline__ uint32_t pack_bf16x2(float lo, float hi) {
    uint32_t d;
    asm("cvt.rn.bf16x2.f32 %0, %1, %2;" : "=r"(d) : "f"(hi), "f"(lo));
    return d;
}
__device__ __forceinline__ void split2(float v0, float v1,
                                       uint32_t& hp, uint32_t& lp) {
    hp = pack_bf16x2(v0, v1);
    float h0 = __uint_as_float(hp << 16);
    float h1 = __uint_as_float(hp & 0xffff0000u);
    lp = pack_bf16x2(v0 - h0, v1 - h1);
}

__device__ __forceinline__ float gelu_exact(float x) {
    return 0.5f * x * (1.0f + erff(x * 0.70710678118654752f));
}

// ---------------------------------------------------------------------------
// Generalized split-bf16 GEMM (3-mma Markidis): C = A @ W(op)
// 3-stage cp.async pipeline, ONE __syncthreads per k-iteration,
// staging at BOTTOM of iteration (validated best placement).
// LOSSP: fuse per-tile (max, sum-exp) partials into the epilogue (head GEMM).
// ---------------------------------------------------------------------------
template<int NT, bool BTRANS>
struct Geom {
    static constexpr int SBb = BTRANS ? (2 * NT + 16) : 80;
    static constexpr int BSZ = BTRANS ? 32 * SBb : NT * 80;
    static constexpr int AL  = 10240;
    static constexpr int BH  = 20480;
    static constexpr int BL  = BH + BSZ;
    static constexpr int BUF = BH + 2 * BSZ;
    static constexpr int SMEM = 3 * BUF;          // 3 stages
};

template<int NT, bool BTRANS, bool BIAS, bool RES, bool GELU,
         bool WC, bool WPL, int ZMODE, bool SWAPXY, bool LOSSP>
__global__ void __launch_bounds__(256, 2) gemm_u(
    const __nv_bfloat16* __restrict__ Ah, const __nv_bfloat16* __restrict__ Al,
    const __nv_bfloat16* __restrict__ Wh, const __nv_bfloat16* __restrict__ Wl,
    const float* __restrict__ bias, const float* __restrict__ Rres,
    float* __restrict__ C,
    __nv_bfloat16* __restrict__ Ch, __nv_bfloat16* __restrict__ Cl,
    __nv_bfloat16* __restrict__ Dh, __nv_bfloat16* __restrict__ Dl,
    __nv_bfloat16* __restrict__ Eh, __nv_bfloat16* __restrict__ El,
    int N, int K, int ldc, size_t sA, size_t sW, size_t sC) {

    using G = Geom<NT, BTRANS>;
    extern __shared__ char smem[];
    const uint32_t sb = (uint32_t)__cvta_generic_to_shared(smem);

    const int m0 = (SWAPXY ? blockIdx.x : blockIdx.y) * 128;
    const int n0 = (SWAPXY ? blockIdx.y : blockIdx.x) * NT;

    const int z = blockIdx.z;
    Ah += z * sA; Al += z * sA;
    Wh += z * sW; Wl += z * sW;
    const size_t cofs = z * sC;

    const int tid  = threadIdx.x;
    const int lane = tid & 31;
    const int wid  = tid >> 5;
    const int gr   = lane >> 2;
    const int tg   = lane & 3;
    const int mw   = (wid & 3) * 32;
    const int nw   = (wid >> 2) * (NT / 2);
    const int lr   = lane & 7, lt = lane >> 3;

    const uint32_t aoff = (uint32_t)((mw + (lt & 1) * 8 + lr) * 80 + (lt >> 1) * 16);
    uint32_t boff;
    if (BTRANS) boff = (uint32_t)(((lt & 1) * 8 + lr) * G::SBb + (nw + (lt >> 1) * 8) * 2);
    else        boff = (uint32_t)((nw + (lt >> 1) * 8 + lr) * 80 + (lt & 1) * 16);

    constexpr int NTW = NT / 16;
    float acc[2][NTW][4];
    #pragma unroll
    for (int mi = 0; mi < 2; mi++)
        #pragma unroll
        for (int nt = 0; nt < NTW; nt++)
            #pragma unroll
            for (int q = 0; q < 4; q++) acc[mi][nt][q] = 0.0f;

    const int NK = K >> 5;

    auto stage = [&](int ib, int buf) {
        const int k0 = ib << 5;
        const uint32_t bb = sb + buf * G::BUF;
        #pragma unroll
        for (int j = 0; j < 2; j++) {
            int c = tid + 256 * j;
            int row = c >> 2, seg = c & 3;
            uint32_t d = bb + (uint32_t)(row * 80 + seg * 16);
            size_t s = (size_t)(m0 + row) * K + k0 + seg * 8;
            cp_async16(d, Ah + s);
            cp_async16(d + G::AL, Al + s);
        }
        if (BTRANS) {
            constexpr int SEGS = NT / 8;
            constexpr int BCH = 32 * SEGS;
            #pragma unroll
            for (int j = 0; j < (BCH + 255) / 256; j++) {
                int c = tid + 256 * j;
                if ((BCH % 256 == 0) || c < BCH) {
                    int kr = c / SEGS, seg = c - kr * SEGS;
                    uint32_t d = bb + G::BH + (uint32_t)(kr * G::SBb + seg * 16);
                    size_t s = (size_t)(k0 + kr) * N + n0 + seg * 8;
                    cp_async16(d, Wh + s);
                    cp_async16(d + G::BSZ, Wl + s);
                }
            }
        } else {
            constexpr int BCH = NT * 4;
            #pragma unroll
            for (int j = 0; j < (BCH + 255) / 256; j++) {
                int c = tid + 256 * j;
                if ((BCH % 256 == 0) || c < BCH) {
                    int row = c >> 2, seg = c & 3;
                    uint32_t d = bb + G::BH + (uint32_t)(row * 80 + seg * 16);
                    size_t s = (size_t)(n0 + row) * K + k0 + seg * 8;
                    cp_async16(d, Wh + s);
                    cp_async16(d + G::BSZ, Wl + s);
                }
            }
        }
    };

    stage(0, 0); CP_COMMIT();
    stage(1, 1); CP_COMMIT();

    for (int ib = 0; ib < NK; ib++) {
        const int buf = ib % 3;
        CP_WAIT1();
        __syncthreads();

        const uint32_t base = sb + buf * G::BUF;
        const uint32_t aHb = base + aoff;
        const uint32_t aLb = base + G::AL + aoff;
        const uint32_t bHb = base + G::BH + boff;
        const uint32_t bLb = base + G::BL + boff;

        #pragma unroll
        for (int ks = 0; ks < 2; ks++) {
            uint32_t ahi[2][4], alo[2][4];
            ldsm_x4(ahi[0], aHb + ks * 32);
            ldsm_x4(ahi[1], aHb + 1280 + ks * 32);
            ldsm_x4(alo[0], aLb + ks * 32);
            ldsm_x4(alo[1], aLb + 1280 + ks * 32);
            #pragma unroll
            for (int g = 0; g < NT / 32; g++) {
                uint32_t bh[4], bl[4];
                if (BTRANS) {
                    ldsm_x4_t(bh, bHb + ks * (16 * G::SBb) + g * 32);
                    ldsm_x4_t(bl, bLb + ks * (16 * G::SBb) + g * 32);
                } else {
                    ldsm_x4(bh, bHb + ks * 32 + g * 1280);
                    ldsm_x4(bl, bLb + ks * 32 + g * 1280);
                }
                const int nt = g * 2;
                mma_bf16(acc[0][nt],     ahi[0], bh[0], bh[1]);
                mma_bf16(acc[1][nt],     ahi[1], bh[0], bh[1]);
                mma_bf16(acc[0][nt + 1], ahi[0], bh[2], bh[3]);
                mma_bf16(acc[1][nt + 1], ahi[1], bh[2], bh[3]);
                mma_bf16(acc[0][nt],     ahi[0], bl[0], bl[1]);
                mma_bf16(acc[1][nt],     ahi[1], bl[0], bl[1]);
                mma_bf16(acc[0][nt + 1], ahi[0], bl[2], bl[3]);
                mma_bf16(acc[1][nt + 1], ahi[1], bl[2], bl[3]);
                mma_bf16(acc[0][nt],     alo[0], bh[0], bh[1]);
                mma_bf16(acc[1][nt],     alo[1], bh[0], bh[1]);
                mma_bf16(acc[0][nt + 1], alo[0], bh[2], bh[3]);
                mma_bf16(acc[1][nt + 1], alo[1], bh[2], bh[3]);
            }
        }
        // Staging at BOTTOM: overlaps the mma tail. Hazard-free without a
        // second barrier: buffer (ib+2)%3 was consumed in iteration ib-1;
        // every warp passed this iteration's __syncthreads.
        if (ib + 2 < NK) stage(ib + 2, (ib + 2) % 3);
        CP_COMMIT();
    }

    #pragma unroll
    for (int mi = 0; mi < 2; mi++) {
        const int r0 = m0 + mw + mi * 16 + gr;
        #pragma unroll
        for (int nt = 0; nt < NTW; nt++) {
            const int c0 = n0 + nw + nt * 8 + tg * 2;
            float2 v0 = make_float2(acc[mi][nt][0], acc[mi][nt][1]);
            float2 v1 = make_float2(acc[mi][nt][2], acc[mi][nt][3]);
            if (BIAS) {
                float2 bv = *(const float2*)(bias + c0);
                v0.x += bv.x; v0.y += bv.y;
                v1.x += bv.x; v1.y += bv.y;
            }
            if (GELU) {
                v0.x = gelu_exact(v0.x); v0.y = gelu_exact(v0.y);
                v1.x = gelu_exact(v1.x); v1.y = gelu_exact(v1.y);
            }
            if (ZMODE == 2) {
                const int sec = n0 / cD;
                const int cc  = c0 - sec * cD;
                const int h   = cc >> 6, d = cc & 63;
                const float scale = (sec == 0) ? 0.125f : 1.0f;
                uint32_t* ph = (uint32_t*)(sec == 0 ? Ch : sec == 1 ? Dh : Eh);
                uint32_t* pl = (uint32_t*)(sec == 0 ? Cl : sec == 1 ? Dl : El);
                const int b = r0 >> 10, t0 = r0 & 1023;
                size_t zb = (size_t)(b * cH + h) * 1024;
                size_t oA = (zb + t0)     * 32 + (d >> 1);
                size_t oB = (zb + t0 + 8) * 32 + (d >> 1);
                uint32_t hp, lp;
                split2(v0.x * scale, v0.y * scale, hp, lp);
                ph[oA] = hp; pl[oA] = lp;
                split2(v1.x * scale, v1.y * scale, hp, lp);
                ph[oB] = hp; pl[oB] = lp;
            } else {
                size_t o0 = cofs + (size_t)r0 * ldc + c0;
                size_t o1 = cofs + (size_t)(r0 + 8) * ldc + c0;
                if (RES) {
                    float2 a0 = *(const float2*)(Rres + o0);
                    float2 a1 = *(const float2*)(Rres + o1);
                    v0.x += a0.x; v0.y += a0.y;
                    v1.x += a1.x; v1.y += a1.y;
                }
                if (WC) {
                    *(float2*)(C + o0) = v0;
                    *(float2*)(C + o1) = v1;
                }
                if (WPL) {
                    uint32_t hp, lp;
                    split2(v0.x, v0.y, hp, lp);
                    ((uint32_t*)Ch)[o0 >> 1] = hp;
                    ((uint32_t*)Cl)[o0 >> 1] = lp;
                    split2(v1.x, v1.y, hp, lp);
                    ((uint32_t*)Ch)[o1 >> 1] = hp;
                    ((uint32_t*)Cl)[o1 >> 1] = lp;
                }
            }
        }
    }

    if (LOSSP) {
        // per-tile (max, sum-exp) partials over this CTA's NT columns.
        float pm[2][2], ps[2][2];
        #pragma unroll
        for (int mi = 0; mi < 2; mi++) {
            #pragma unroll
            for (int rh = 0; rh < 2; rh++) {
                float m = -INFINITY;
                #pragma unroll
                for (int nt = 0; nt < NTW; nt++)
                    m = fmaxf(m, fmaxf(acc[mi][nt][rh * 2], acc[mi][nt][rh * 2 + 1]));
                float s = 0.0f;
                #pragma unroll
                for (int nt = 0; nt < NTW; nt++)
                    s += __expf(acc[mi][nt][rh * 2] - m)
                       + __expf(acc[mi][nt][rh * 2 + 1] - m);
                #pragma unroll
                for (int o = 1; o <= 2; o <<= 1) {
                    float mo = __shfl_xor_sync(0xffffffffu, m, o);
                    float so = __shfl_xor_sync(0xffffffffu, s, o);
                    float nm = fmaxf(m, mo);
                    s = s * __expf(m - nm) + so * __expf(mo - nm);
                    m = nm;
                }
                pm[mi][rh] = m; ps[mi][rh] = s;
            }
        }
        __syncthreads();
        float* sp = (float*)smem;                // [2 halves][128 rows][2]
        if (tg == 0) {
            int half = wid >> 2;
            #pragma unroll
            for (int mi = 0; mi < 2; mi++)
                #pragma unroll
                for (int rh = 0; rh < 2; rh++) {
                    int row = mw + mi * 16 + gr + rh * 8;
                    sp[(half * 128 + row) * 2 + 0] = pm[mi][rh];
                    sp[(half * 128 + row) * 2 + 1] = ps[mi][rh];
                }
        }
        __syncthreads();
        if (tid < 128) {
            float m0v = sp[tid * 2],           s0v = sp[tid * 2 + 1];
            float m1v = sp[(128 + tid) * 2],   s1v = sp[(128 + tid) * 2 + 1];
            float nm = fmaxf(m0v, m1v);
            float sc = s0v * __expf(m0v - nm) + s1v * __expf(m1v - nm);
            g_part[(size_t)(n0 >> 7) * cM + (m0 + tid)] = make_float2(nm, sc);
        }
    }
}

// ---------------------------------------------------------------------------
// Fused flash attention (split-bf16 mma, online softmax)
// 1D grid in LPT (longest-processing-time-first) order: heaviest q-blocks
// launch first so backfill packs the causal-imbalanced work tightly.
// ---------------------------------------------------------------------------
constexpr int F_SQ   = 144;
constexpr int F_PL   = 128 * F_SQ;
constexpr int F_KV0  = 2 * F_PL;
constexpr int F_KVSZ = 4 * F_PL;
constexpr int FLASH_SMEM = 2 * F_PL + 2 * F_KVSZ;  // 184320

__global__ void __launch_bounds__(256, 1) flash_kernel(
    const __nv_bfloat16* __restrict__ qh, const __nv_bfloat16* __restrict__ ql,
    const __nv_bfloat16* __restrict__ kh, const __nv_bfloat16* __restrict__ kl,
    const __nv_bfloat16* __restrict__ vh, const __nv_bfloat16* __restrict__ vl,
    __nv_bfloat16* __restrict__ yh, __nv_bfloat16* __restrict__ yl) {

    extern __shared__ char smem[];
    const uint32_t sb = (uint32_t)__cvta_generic_to_shared(smem);
    // LPT remap: idx 0..47 -> qb=7 (8 kv-blocks), idx 48..95 -> qb=6, ...
    const int idx1 = blockIdx.x;
    const int qb = (cT / 128 - 1) - idx1 / cZ;
    const int z  = idx1 % cZ;
    const int q0 = qb * 128;
    const int tid  = threadIdx.x;
    const int lane = tid & 31;
    const int wid  = tid >> 5;
    const int gr   = lane >> 2;
    const int tg   = lane & 3;
    const int wq   = wid * 16;
    const int lr   = lane & 7, lt = lane >> 3;

    const __nv_bfloat16* qhz = qh + (size_t)z * cQH;
    const __nv_bfloat16* qlz = ql + (size_t)z * cQH;
    const __nv_bfloat16* khz = kh + (size_t)z * cQH;
    const __nv_bfloat16* klz = kl + (size_t)z * cQH;
    const __nv_bfloat16* vhz = vh + (size_t)z * cQH;
    const __nv_bfloat16* vlz = vl + (size_t)z * cQH;

    #pragma unroll
    for (int j = 0; j < 4; j++) {
        int c = tid + 256 * j;
        int row = c >> 3, seg = c & 7;
        uint32_t d = sb + (uint32_t)(row * F_SQ + seg * 16);
        size_t s = (size_t)(q0 + row) * cHD + seg * 8;
        cp_async16(d, qhz + s);
        cp_async16(d + F_PL, qlz + s);
    }
    auto stageKV = [&](int kb, int buf) {
        const uint32_t bb = sb + F_KV0 + buf * F_KVSZ;
        #pragma unroll
        for (int j = 0; j < 4; j++) {
            int c = tid + 256 * j;
            int row = c >> 3, seg = c & 7;
            uint32_t d = bb + (uint32_t)(row * F_SQ + seg * 16);
            size_t s = (size_t)(kb * 128 + row) * cHD + seg * 8;
            cp_async16(d, khz + s);
            cp_async16(d + F_PL, klz + s);
            cp_async16(d + 2 * F_PL, vhz + s);
            cp_async16(d + 3 * F_PL, vlz + s);
        }
    };

    stageKV(0, 0);
    CP_COMMIT();
    if (qb >= 1) { stageKV(1, 1); CP_COMMIT(); }

    float mrow[2] = { -INFINITY, -INFINITY };
    float lrow[2] = { 0.0f, 0.0f };
    float oacc[8][4];
    #pragma unroll
    for (int nt = 0; nt < 8; nt++)
        #pragma unroll
        for (int q = 0; q < 4; q++) oacc[nt][q] = 0.0f;

    uint32_t qfh[4][4], qfl[4][4];
    bool qloaded = false;

    const uint32_t q_aoff = (uint32_t)((wq + (lt & 1) * 8 + lr) * F_SQ + (lt >> 1) * 16);
    const uint32_t k_boff = (uint32_t)(((lt >> 1) * 8 + lr) * F_SQ + (lt & 1) * 16);
    const uint32_t v_boff = (uint32_t)(((lt & 1) * 8 + lr) * F_SQ + (lt >> 1) * 16);

    for (int kb = 0; kb <= qb; kb++) {
        if (kb < qb) { CP_WAIT1(); } else { CP_WAIT0(); }
        __syncthreads();

        if (!qloaded) {
            #pragma unroll
            for (int ks = 0; ks < 4; ks++) {
                ldsm_x4(qfh[ks], sb + q_aoff + ks * 32);
                ldsm_x4(qfl[ks], sb + F_PL + q_aoff + ks * 32);
            }
            qloaded = true;
        }

        const uint32_t kvb = sb + F_KV0 + (kb & 1) * F_KVSZ;

        float s[16][4];
        #pragma unroll
        for (int nt = 0; nt < 16; nt++)
            #pragma unroll
            for (int q = 0; q < 4; q++) s[nt][q] = 0.0f;

        #pragma unroll
        for (int ks = 0; ks < 4; ks++) {
            #pragma unroll
            for (int g = 0; g < 8; g++) {
                uint32_t bh[4], bl[4];
                uint32_t addr = kvb + k_boff + (uint32_t)(g * 16 * F_SQ) + ks * 32;
                ldsm_x4(bh, addr);
                ldsm_x4(bl, addr + F_PL);
                const int nt = g * 2;
                mma_bf16(s[nt],     qfh[ks], bh[0], bh[1]);
                mma_bf16(s[nt + 1], qfh[ks], bh[2], bh[3]);
                mma_bf16(s[nt],     qfh[ks], bl[0], bl[1]);
                mma_bf16(s[nt + 1], qfh[ks], bl[2], bl[3]);
                mma_bf16(s[nt],     qfl[ks], bh[0], bh[1]);
                mma_bf16(s[nt + 1], qfl[ks], bh[2], bh[3]);
            }
        }

        if (kb == qb) {
            const int r0 = wq + gr, r1 = wq + gr + 8;
            #pragma unroll
            for (int nt = 0; nt < 16; nt++) {
                const int c0 = nt * 8 + tg * 2;
                if (c0     > r0) s[nt][0] = -1e30f;
                if (c0 + 1 > r0) s[nt][1] = -1e30f;
                if (c0     > r1) s[nt][2] = -1e30f;
                if (c0 + 1 > r1) s[nt][3] = -1e30f;
            }
        }

        float mn0 = -INFINITY, mn1 = -INFINITY;
        #pragma unroll
        for (int nt = 0; nt < 16; nt++) {
            mn0 = fmaxf(mn0, fmaxf(s[nt][0], s[nt][1]));
            mn1 = fmaxf(mn1, fmaxf(s[nt][2], s[nt][3]));
        }
        mn0 = fmaxf(mn0, __shfl_xor_sync(0xffffffffu, mn0, 1));
        mn0 = fmaxf(mn0, __shfl_xor_sync(0xffffffffu, mn0, 2));
        mn1 = fmaxf(mn1, __shfl_xor_sync(0xffffffffu, mn1, 1));
        mn1 = fmaxf(mn1, __shfl_xor_sync(0xffffffffu, mn1, 2));
        float mnew0 = fmaxf(mrow[0], mn0);
        float mnew1 = fmaxf(mrow[1], mn1);
        float al0 = __expf(mrow[0] - mnew0);
        float al1 = __expf(mrow[1] - mnew1);
        mrow[0] = mnew0; mrow[1] = mnew1;

        float rs0 = 0.0f, rs1 = 0.0f;
        #pragma unroll
        for (int nt = 0; nt < 16; nt++) {
            s[nt][0] = __expf(s[nt][0] - mnew0);
            s[nt][1] = __expf(s[nt][1] - mnew0);
            s[nt][2] = __expf(s[nt][2] - mnew1);
            s[nt][3] = __expf(s[nt][3] - mnew1);
            rs0 += s[nt][0] + s[nt][1];
            rs1 += s[nt][2] + s[nt][3];
        }
        rs0 += __shfl_xor_sync(0xffffffffu, rs0, 1);
        rs0 += __shfl_xor_sync(0xffffffffu, rs0, 2);
        rs1 += __shfl_xor_sync(0xffffffffu, rs1, 1);
        rs1 += __shfl_xor_sync(0xffffffffu, rs1, 2);
        lrow[0] = lrow[0] * al0 + rs0;
        lrow[1] = lrow[1] * al1 + rs1;

        #pragma unroll
        for (int nt = 0; nt < 8; nt++) {
            oacc[nt][0] *= al0; oacc[nt][1] *= al0;
            oacc[nt][2] *= al1; oacc[nt][3] *= al1;
        }

        #pragma unroll
        for (int ks = 0; ks < 8; ks++) {
            uint32_t pah[4], pal[4];
            uint32_t h0, l0;
            split2(s[2*ks][0],   s[2*ks][1],   h0, l0); pah[0] = h0; pal[0] = l0;
            split2(s[2*ks][2],   s[2*ks][3],   h0, l0); pah[1] = h0; pal[1] = l0;
            split2(s[2*ks+1][0], s[2*ks+1][1], h0, l0); pah[2] = h0; pal[2] = l0;
            split2(s[2*ks+1][2], s[2*ks+1][3], h0, l0); pah[3] = h0; pal[3] = l0;
            #pragma unroll
            for (int g = 0; g < 4; g++) {
                uint32_t bvh[4], bvl[4];
                uint32_t addr = kvb + 2 * F_PL + v_boff
                              + (uint32_t)(ks * 16 * F_SQ) + g * 32;
                ldsm_x4_t(bvh, addr);
                ldsm_x4_t(bvl, addr + F_PL);
                const int nt = g * 2;
                mma_bf16(oacc[nt],     pah, bvh[0], bvh[1]);
                mma_bf16(oacc[nt + 1], pah, bvh[2], bvh[3]);
                mma_bf16(oacc[nt],     pah, bvl[0], bvl[1]);
                mma_bf16(oacc[nt + 1], pah, bvl[2], bvl[3]);
                mma_bf16(oacc[nt],     pal, bvh[0], bvh[1]);
                mma_bf16(oacc[nt + 1], pal, bvh[2], bvh[3]);
            }
        }

        __syncthreads();
        if (kb + 2 <= qb) { stageKV(kb + 2, kb & 1); CP_COMMIT(); }
    }

    const float inv0 = 1.0f / lrow[0];
    const float inv1 = 1.0f / lrow[1];
    const int b = z / cH, h = z % cH;
    const int r0 = b * cT + q0 + wq + gr;
    #pragma unroll
    for (int nt = 0; nt < 8; nt++) {
        const int c0 = h * cHD + nt * 8 + tg * 2;
        uint32_t hp, lp;
        split2(oacc[nt][0] * inv0, oacc[nt][1] * inv0, hp, lp);
        size_t o0 = ((size_t)r0 * cD + c0) >> 1;
        ((uint32_t*)yh)[o0] = hp; ((uint32_t*)yl)[o0] = lp;
        split2(oacc[nt][2] * inv1, oacc[nt][3] * inv1, hp, lp);
        size_t o1 = ((size_t)(r0 + 8) * cD + c0) >> 1;
        ((uint32_t*)yh)[o1] = hp; ((uint32_t*)yl)[o1] = lp;
    }
}

// ---------------------------------------------------------------------------
// Block reductions (blockDim.x == 256)
// ---------------------------------------------------------------------------
__device__ __forceinline__ float blockReduceSum(float v) {
    __shared__ float sh[8];
    #pragma unroll
    for (int o = 16; o; o >>= 1) v += __shfl_xor_sync(0xffffffffu, v, o);
    int w = threadIdx.x >> 5, l = threadIdx.x & 31;
    __syncthreads();
    if (l == 0) sh[w] = v;
    __syncthreads();
    if (w == 0) {
        v = (l < 8) ? sh[l] : 0.0f;
        #pragma unroll
        for (int o = 16; o; o >>= 1) v += __shfl_xor_sync(0xffffffffu, v, o);
        if (l == 0) sh[0] = v;
    }
    __syncthreads();
    return sh[0];
}

// ---------------------------------------------------------------------------
// Small kernels
// ---------------------------------------------------------------------------
__global__ void __launch_bounds__(256) split_all_kernel(
    const float* __restrict__ wa, const float* __restrict__ wp,
    const float* __restrict__ wf, const float* __restrict__ wo,
    const float* __restrict__ wh,
    __nv_bfloat16* wah, __nv_bfloat16* wal,
    __nv_bfloat16* wph, __nv_bfloat16* wpl,
    __nv_bfloat16* wfh, __nv_bfloat16* wfl,
    __nv_bfloat16* woh, __nv_bfloat16* wol,
    __nv_bfloat16* whh, __nv_bfloat16* whl) {
    size_t q = ((size_t)blockIdx.x * 256 + threadIdx.x) * 2;
    const float* src; __nv_bfloat16 *hi, *lo; size_t base;
    if (q < SQ0)      { src = wa; hi = wah; lo = wal; base = 0;   }
    else if (q < SQ1) { src = wp; hi = wph; lo = wpl; base = SQ0; }
    else if (q < SQ2) { src = wf; hi = wfh; lo = wfl; base = SQ1; }
    else if (q < SQ3) { src = wo; hi = woh; lo = wol; base = SQ2; }
    else              { src = wh; hi = whh; lo = whl; base = SQ3; }
    size_t lq = q - base;
    #pragma unroll
    for (int j = 0; j < 2; j++) {
        float4 v = *(const float4*)(src + (lq + j) * 4);
        uint32_t h0, l0, h1, l1;
        split2(v.x, v.y, h0, l0);
        split2(v.z, v.w, h1, l1);
        ((uint2*)hi)[lq + j] = make_uint2(h0, h1);
        ((uint2*)lo)[lq + j] = make_uint2(l0, l1);
    }
}

__global__ void __launch_bounds__(256) embed_ln_kernel(
    const int* __restrict__ idx,
    const float* __restrict__ wte, const float* __restrict__ wpe,
    const float* __restrict__ g, const float* __restrict__ b,
    float* __restrict__ x,
    __nv_bfloat16* __restrict__ oh, __nv_bfloat16* __restrict__ ol) {
    const int row = blockIdx.x;
    const int t = threadIdx.x;
    const int tok = idx[row];
    const int tp  = row & (cT - 1);
    float v0 = wte[(size_t)tok * cD + t]       + wpe[(size_t)tp * cD + t];
    float v1 = wte[(size_t)tok * cD + t + 256] + wpe[(size_t)tp * cD + t + 256];
    float v2 = wte[(size_t)tok * cD + t + 512] + wpe[(size_t)tp * cD + t + 512];
    float* xr = x + (size_t)row * cD;
    xr[t] = v0; xr[t + 256] = v1; xr[t + 512] = v2;
    float s  = blockReduceSum(v0 + v1 + v2);
    float s2 = blockReduceSum(v0 * v0 + v1 * v1 + v2 * v2);
    const float inv = 1.0f / cD;
    float mu  = s * inv;
    float var = s2 * inv - mu * mu;
    float rs  = rsqrtf(var + 1e-5f);
    #pragma unroll
    for (int j = 0; j < 3; j++) {
        int d = t + j * 256;
        float val = (((j == 0) ? v0 : (j == 1) ? v1 : v2) - mu) * rs * g[d] + b[d];
        __nv_bfloat16 h = __float2bfloat16_rn(val);
        oh[(size_t)row * cD + d] = h;
        ol[(size_t)row * cD + d] = __float2bfloat16_rn(val - __bfloat162float(h));
    }
}

__global__ void __launch_bounds__(256) ln_kernel(const float* __restrict__ x,
                                                 const float* __restrict__ g,
                                                 const float* __restrict__ b,
                                                 __nv_bfloat16* __restrict__ oh,
                                                 __nv_bfloat16* __restrict__ ol) {
    const int row = blockIdx.x;
    const float* xr = x + (size_t)row * cD;
    const int t = threadIdx.x;
    float v0 = xr[t], v1 = xr[t + 256], v2 = xr[t + 512];
    float s  = blockReduceSum(v0 + v1 + v2);
    float s2 = blockReduceSum(v0 * v0 + v1 * v1 + v2 * v2);
    const float inv = 1.0f / cD;
    float mu  = s * inv;
    float var = s2 * inv - mu * mu;
    float rs  = rsqrtf(var + 1e-5f);
    #pragma unroll
    for (int j = 0; j < 3; j++) {
        int d = t + j * 256;
        float val = (((j == 0) ? v0 : (j == 1) ? v1 : v2) - mu) * rs * g[d] + b[d];
        __nv_bfloat16 h = __float2bfloat16_rn(val);
        oh[(size_t)row * cD + d] = h;
        ol[(size_t)row * cD + d] = __float2bfloat16_rn(val - __bfloat162float(h));
    }
}

__global__ void __launch_bounds__(256) loss_combine_kernel(
    const float* __restrict__ logits, const int* __restrict__ tgt,
    float* __restrict__ nll) {
    const int r = blockIdx.x;
    float m = -INFINITY, s = 0.0f;
    for (int t = threadIdx.x; t < cVT; t += 256) {
        float2 p = g_part[(size_t)t * cM + r];
        float nm = fmaxf(m, p.x);
        s = s * __expf(m - nm) + p.y * __expf(p.x - nm);
        m = nm;
    }
    #pragma unroll
    for (int o = 16; o; o >>= 1) {
        float mo = __shfl_xor_sync(0xffffffffu, m, o);
        float so = __shfl_xor_sync(0xffffffffu, s, o);
        float nm = fmaxf(m, mo);
        s = s * __expf(m - nm) + so * __expf(mo - nm);
        m = nm;
    }
    __shared__ float shm[8], shs[8];
    int w = threadIdx.x >> 5, l = threadIdx.x & 31;
    if (l == 0) { shm[w] = m; shs[w] = s; }
    __syncthreads();
    if (w == 0) {
        m = (l < 8) ? shm[l] : -INFINITY;
        s = (l < 8) ? shs[l] : 0.0f;
        #pragma unroll
        for (int o = 4; o; o >>= 1) {
            float mo = __shfl_xor_sync(0xffffffffu, m, o);
            float so = __shfl_xor_sync(0xffffffffu, s, o);
            float nm = fmaxf(m, mo);
            s = s * __expf(m - nm) + so * __expf(mo - nm);
            m = nm;
        }
        if (l == 0)
            nll[r] = -(logits[(size_t)r * cV + tgt[r]] - m - logf(s));
    }
}

__global__ void __launch_bounds__(256) loss_reduce_kernel(const float* __restrict__ nll,
                                                          float* __restrict__ out) {
    float s = 0.0f;
    for (int i = threadIdx.x; i < cM; i += 256) s += nll[i];
    s = blockReduceSum(s);
    if (threadIdx.x == 0) *out = s / (float)cM;
}

// ---------------------------------------------------------------------------
// Launch
// ---------------------------------------------------------------------------
template<typename T> static T* sym(const void* s) {
    void* p; cudaGetSymbolAddress(&p, s); return (T*)p;
}

using bf16 = __nv_bfloat16;

//               NT  BT    BIAS  RES   GELU  WC    WPL   ZM SWAP  LOSSP
#define GQKV  gemm_u<128,true ,false,false,false,false,false,2,false,false>
#define GHEAD gemm_u<128,true ,false,false,false,true ,false,0,true ,true >
#define GPROJ gemm_u<96 ,true ,false,true ,false,true ,false,0,false,false>
#define GFC   gemm_u<128,true ,true ,false,true ,false,true ,0,false,false>
#define GOUT  gemm_u<96 ,true ,true ,true ,false,true ,false,0,false,false>

extern "C" void kernel_launch(void* const* d_in, const int* in_sizes, int n_in,
                              void* d_out, int out_size) {
    const int*   idx    = (const int*)  d_in[0];
    const int*   tgt    = (const int*)  d_in[1];
    const float* wte    = (const float*)d_in[2];
    const float* wpe    = (const float*)d_in[3];
    const float* ln1_g  = (const float*)d_in[4];
    const float* ln1_b  = (const float*)d_in[5];
    const float* w_attn = (const float*)d_in[6];
    const float* w_proj = (const float*)d_in[7];
    const float* ln2_g  = (const float*)d_in[8];
    const float* ln2_b  = (const float*)d_in[9];
    const float* w_fc   = (const float*)d_in[10];
    const float* b_fc   = (const float*)d_in[11];
    const float* w_out  = (const float*)d_in[12];
    const float* b_out  = (const float*)d_in[13];
    const float* lnf_g  = (const float*)d_in[14];
    const float* lnf_b  = (const float*)d_in[15];
    const float* w_head = (const float*)d_in[16];
    float* logits = (float*)d_out;

    float* x   = sym<float>(g_x);
    float* nll = sym<float>(g_nll);
    bf16 *lnh = sym<bf16>(g_ln_h), *lnl = sym<bf16>(g_ln_l);
    bf16 *yh  = sym<bf16>(g_y_h),  *yl  = sym<bf16>(g_y_l);
    bf16 *fch = sym<bf16>(g_fc_h), *fcl = sym<bf16>(g_fc_l);
    bf16 *qh  = sym<bf16>(g_q_h),  *ql  = sym<bf16>(g_q_l);
    bf16 *kh  = sym<bf16>(g_k_h),  *kl  = sym<bf16>(g_k_l);
    bf16 *vh  = sym<bf16>(g_v_h),  *vl  = sym<bf16>(g_v_l);
    bf16 *wah = sym<bf16>(g_wa_h), *wal = sym<bf16>(g_wa_l);
    bf16 *wph = sym<bf16>(g_wp_h), *wpl = sym<bf16>(g_wp_l);
    bf16 *wfh = sym<bf16>(g_wf_h), *wfl = sym<bf16>(g_wf_l);
    bf16 *woh = sym<bf16>(g_wo_h), *wol = sym<bf16>(g_wo_l);
    bf16 *whh = sym<bf16>(g_wh_h), *whl = sym<bf16>(g_wh_l);

    constexpr int SM128T = Geom<128, true>::SMEM;  // 113664
    constexpr int SM96T  = Geom<96,  true>::SMEM;  // 101376

    cudaFuncSetAttribute((const void*)GQKV,  cudaFuncAttributeMaxDynamicSharedMemorySize, SM128T);
    cudaFuncSetAttribute((const void*)GHEAD, cudaFuncAttributeMaxDynamicSharedMemorySize, SM128T);
    cudaFuncSetAttribute((const void*)GPROJ, cudaFuncAttributeMaxDynamicSharedMemorySize, SM96T);
    cudaFuncSetAttribute((const void*)GFC,   cudaFuncAttributeMaxDynamicSharedMemorySize, SM128T);
    cudaFuncSetAttribute((const void*)GOUT,  cudaFuncAttributeMaxDynamicSharedMemorySize, SM96T);
    cudaFuncSetAttribute((const void*)flash_kernel,
                         cudaFuncAttributeMaxDynamicSharedMemorySize, FLASH_SMEM);

    split_all_kernel<<<(int)(SQ4 / 512), 256>>>(
        w_attn, w_proj, w_fc, w_out, w_head,
        wah, wal, wph, wpl, wfh, wfl, woh, wol, whh, whl);

    embed_ln_kernel<<<cM, 256>>>(idx, wte, wpe, ln1_g, ln1_b, x, lnh, lnl);

    for (int l = 0; l < cL; l++) {
        if (l > 0)
            ln_kernel<<<cM, 256>>>(x, ln1_g + l * cD, ln1_b + l * cD, lnh, lnl);
        GQKV<<<dim3(cD3 / 128, cM / 128, 1), 256, SM128T>>>(
            lnh, lnl, wah + (size_t)l * cD * cD3, wal + (size_t)l * cD * cD3,
            nullptr, nullptr, nullptr, qh, ql, kh, kl, vh, vl, cD3, cD, cD3, 0, 0, 0);
        flash_kernel<<<(cT / 128) * cZ, 256, FLASH_SMEM>>>(
            qh, ql, kh, kl, vh, vl, yh, yl);
        GPROJ<<<dim3(cD / 96, cM / 128, 1), 256, SM96T>>>(
            yh, yl, wph + (size_t)l * cD * cD, wpl + (size_t)l * cD * cD,
            nullptr, x, x, nullptr, nullptr, nullptr, nullptr, nullptr, nullptr,
            cD, cD, cD, 0, 0, 0);
        ln_kernel<<<cM, 256>>>(x, ln2_g + l * cD, ln2_b + l * cD, lnh, lnl);
        GFC<<<dim3(cDF / 128, cM / 128, 1), 256, SM128T>>>(
            lnh, lnl, wfh + (size_t)l * cD * cDF, wfl + (size_t)l * cD * cDF,
            b_fc + l * cDF, nullptr, nullptr, fch, fcl, nullptr, nullptr, nullptr, nullptr,
            cDF, cD, cDF, 0, 0, 0);
        GOUT<<<dim3(cD / 96, cM / 128, 1), 256, SM96T>>>(
            fch, fcl, woh + (size_t)l * cDF * cD, wol + (size_t)l * cDF * cD,
            b_out + l * cD, x, x, nullptr, nullptr, nullptr, nullptr, nullptr, nullptr,
            cD, cDF, cD, 0, 0, 0);
    }

    ln_kernel<<<cM, 256>>>(x, lnf_g, lnf_b, lnh, lnl);
    GHEAD<<<dim3(cM / 128, cV / 128, 1), 256, SM128T>>>(
        lnh, lnl, whh, whl, nullptr, nullptr, logits, nullptr, nullptr,
        nullptr, nullptr, nullptr, nullptr, cV, cD, cV, 0, 0, 0);

    if (out_size >= cM * cV + 1) {
        loss_combine_kernel<<<cM, 256>>>(logits, tgt, nll);
        loss_reduce_kernel<<<1, 256>>>(nll, logits + (size_t)cM * cV);
    }
}